// round 10
// baseline (speedup 1.0000x reference)
#include <cuda_runtime.h>
#include <math.h>

#define T_TOK 2048
#define HDIM  2560
#define NEXP  8
#define ITXT  1536
#define IIMG  512
#define ISH   3072

// ---------------- scratch (static device globals; no allocs allowed) ----------
__device__ int   d_count[16];
__device__ int   d_slot_tok[16][T_TOK];
__device__ float d_slot_wt [16][T_TOK];
__device__ float d_x32 [(size_t)T_TOK * HDIM];            // pre-rounded X (tf32)
__device__ float d_g_text[(size_t)NEXP * T_TOK * ITXT];   // raw G
__device__ float d_h_text[(size_t)NEXP * T_TOK * ITXT];   // h = swiglu
__device__ float d_g_img [(size_t)NEXP * T_TOK * IIMG];
__device__ float d_h_img [(size_t)NEXP * T_TOK * IIMG];
__device__ float d_g_sh  [(size_t)T_TOK * ISH];
__device__ float d_mid_sh[(size_t)T_TOK * ISH];
__device__ float d_ytok  [(size_t)T_TOK * 2 * HDIM];

// ---------------- helpers ----------------------------------------------------
__device__ __forceinline__ unsigned ld_tf32(const float* p) {
    unsigned u;
    asm("cvt.rna.tf32.f32 %0, %1;" : "=r"(u) : "f"(*p));
    return u;
}
__device__ __forceinline__ float rnd_tf32(float x) {
    unsigned u;
    asm("cvt.rna.tf32.f32 %0, %1;" : "=r"(u) : "f"(x));
    return __uint_as_float(u);
}

__device__ __forceinline__ void mma_tf32(float c[4], const unsigned a[4],
                                         unsigned b0, unsigned b1) {
    asm volatile(
        "mma.sync.aligned.m16n8k8.row.col.f32.tf32.tf32.f32 "
        "{%0,%1,%2,%3}, {%4,%5,%6,%7}, {%8,%9}, {%0,%1,%2,%3};"
        : "+f"(c[0]), "+f"(c[1]), "+f"(c[2]), "+f"(c[3])
        : "r"(a[0]), "r"(a[1]), "r"(a[2]), "r"(a[3]), "r"(b0), "r"(b1));
}

__device__ __forceinline__ void ldsm_x4(unsigned& r0, unsigned& r1,
                                        unsigned& r2, unsigned& r3,
                                        unsigned addr) {
    asm volatile("ldmatrix.sync.aligned.m8n8.x4.shared.b16 {%0,%1,%2,%3}, [%4];"
                 : "=r"(r0), "=r"(r1), "=r"(r2), "=r"(r3) : "r"(addr));
}

__device__ __forceinline__ void cp16(void* smem, const void* g, int sz) {
    unsigned s = (unsigned)__cvta_generic_to_shared(smem);
    asm volatile("cp.async.cg.shared.global [%0], [%1], 16, %2;"
                 :: "r"(s), "l"(g), "r"(sz));
}
__device__ __forceinline__ void cp_commit() {
    asm volatile("cp.async.commit_group;");
}
template <int N> __device__ __forceinline__ void cp_wait() {
    asm volatile("cp.async.wait_group %0;" :: "n"(N));
}

// ---------------- init / pre-round -------------------------------------------
__global__ void zero_counts_kernel() {
    if (threadIdx.x < 16) d_count[threadIdx.x] = 0;
}

__global__ void preround_x_kernel(const float* __restrict__ x) {
    int i = blockIdx.x * blockDim.x + threadIdx.x;
    const int total = T_TOK * HDIM / 4;
    if (i >= total) return;
    float4 v = reinterpret_cast<const float4*>(x)[i];
    float4 w;
    w.x = rnd_tf32(v.x); w.y = rnd_tf32(v.y);
    w.z = rnd_tf32(v.z); w.w = rnd_tf32(v.w);
    reinterpret_cast<float4*>(d_x32)[i] = w;
}

// ---------------- routing -----------------------------------------------------
// visual_token_mask: bool in reference -> promoted to int32 by the harness.
__global__ void route_kernel(const float* __restrict__ x,
                             const int* __restrict__ vmask,
                             const float* __restrict__ tgate,
                             const float* __restrict__ igate) {
    int t = blockIdx.x;
    int wid = threadIdx.x >> 5, lane = threadIdx.x & 31;
    bool vis = vmask[t] != 0;
    const float* gw = (vis ? igate : tgate) + (size_t)wid * HDIM;
    const float* xr = x + (size_t)t * HDIM;
    float s = 0.f;
    for (int i = lane; i < HDIM; i += 32) s += xr[i] * gw[i];
#pragma unroll
    for (int o = 16; o; o >>= 1) s += __shfl_xor_sync(0xffffffffu, s, o);
    __shared__ float logit[NEXP];
    if (lane == 0) logit[wid] = s;
    __syncthreads();
    if (threadIdx.x == 0) {
        float mx = logit[0];
#pragma unroll
        for (int e = 1; e < NEXP; e++) mx = fmaxf(mx, logit[e]);
        float p[NEXP];
#pragma unroll
        for (int e = 0; e < NEXP; e++) p[e] = expf(logit[e] - mx);
        int i0 = 0;
#pragma unroll
        for (int e = 1; e < NEXP; e++) if (p[e] > p[i0]) i0 = e;
        int i1 = (i0 == 0) ? 1 : 0;
#pragma unroll
        for (int e = 0; e < NEXP; e++)
            if (e != i0 && p[e] > p[i1]) i1 = e;
        float denom = p[i0] + p[i1];
        float w0 = p[i0] / denom;
        float w1 = p[i1] / denom;
        int base = vis ? 8 : 0;
        int g0 = base + i0;
        int g1 = base + i1;
        int pos0 = atomicAdd(&d_count[g0], 1);
        d_slot_tok[g0][pos0] = t * 2 + 0;
        d_slot_wt [g0][pos0] = w0;
        int pos1 = atomicAdd(&d_count[g1], 1);
        d_slot_tok[g1][pos1] = t * 2 + 1;
        d_slot_wt [g1][pos1] = w1;
    }
}

// ---------------- unified GEMM ------------------------------------------------
// C[128x64] per CTA, BK=32, 2-stage cp.async, 8 warps as 2(m) x 4(n),
// warp tile 64x16 (fm=4, fn=2) -> each B fragment feeds 4 MMAs.
// epi: 0 = store raw, 1 = swiglu (h = rnd(silu(g)*u)), 2 = scatter+scale,
//      3 = direct store.
struct GSmem {
    float As[2][128][36];
    float Bs[2][32][72];
    int   srcs[128];
};

__global__ __launch_bounds__(256, 3)
void gemm_kernel(const float* __restrict__ A_base,
                 const float* __restrict__ B_base,
                 float* __restrict__ C_base,
                 const float* __restrict__ G_base,
                 int K, int N, int sgbase, int a_gather, int epi,
                 size_t a_estride, size_t c_estride) {
    extern __shared__ char smem_raw[];
    GSmem* sm = reinterpret_cast<GSmem*>(smem_raw);

    int e = blockIdx.z;
    const int* slot = nullptr;
    const float* wts = nullptr;
    int M;
    if (sgbase >= 0) {
        M = d_count[sgbase + e];
        slot = d_slot_tok[sgbase + e];
        wts  = d_slot_wt [sgbase + e];
    } else {
        M = T_TOK;
    }
    int m0 = blockIdx.y * 128;
    if (m0 >= M) return;
    int n0 = blockIdx.x * 64;

    const float* A = A_base + (size_t)e * a_estride;
    const float* B = B_base + (size_t)e * K * N;
    float* C = C_base + (size_t)e * c_estride;
    const float* G = G_base ? G_base + (size_t)e * c_estride : nullptr;

    int tid = threadIdx.x;
    if (tid < 128) {
        int gr = m0 + tid;
        int s = -1;
        if (gr < M) s = (a_gather && slot) ? (slot[gr] >> 1) : gr;
        sm->srcs[tid] = s;
    }
    __syncthreads();

    int warp = tid >> 5, lane = tid & 31;
    int wm = warp >> 2, wn = warp & 3;     // 2 x 4 warp grid
    int ar = tid >> 3;            // A loader rows 0..31 (stride 32)
    int ac = (tid & 7) * 4;
    int bkr = tid >> 4;           // B loader k-rows 0..15 (stride 16)
    int bc  = (tid & 15) * 4;

    int asrc[4];
#pragma unroll
    for (int j = 0; j < 4; j++) asrc[j] = sm->srcs[ar + j * 32];

    // ldmatrix base: fm fragment = 16 rows x 8 k via 4 8x8 b16 matrices
    unsigned As0 = (unsigned)__cvta_generic_to_shared(&sm->As[0][0][0]);
    int arow = wm * 64 + (lane & 7) + ((lane >> 3) & 1) * 8;
    int acol = (lane >> 4) * 4;
    unsigned aaddr = As0 + (unsigned)((arow * 36 + acol) * 4);
    const unsigned AFM    = 16u * 36u * 4u;     // +16 rows per fm
    const unsigned ASTAGE = 128u * 36u * 4u;

    float cc[4][2][4];
#pragma unroll
    for (int a = 0; a < 4; a++)
#pragma unroll
        for (int b = 0; b < 2; b++)
#pragma unroll
            for (int c = 0; c < 4; c++) cc[a][b][c] = 0.f;

    auto load_tile = [&](int kk, int st) {
        int k0 = kk * 32;
#pragma unroll
        for (int j = 0; j < 4; j++) {
            int r = ar + j * 32;
            int s = asrc[j];
            cp16(&sm->As[st][r][ac],
                 A + (size_t)(s >= 0 ? s : 0) * K + k0 + ac,
                 s >= 0 ? 16 : 0);
        }
#pragma unroll
        for (int j = 0; j < 2; j++) {
            int kr = bkr + j * 16;
            cp16(&sm->Bs[st][kr][bc], B + (size_t)(k0 + kr) * N + n0 + bc, 16);
        }
        cp_commit();
    };

    int kiters = K >> 5;
    load_tile(0, 0);

    for (int kk = 0; kk < kiters; kk++) {
        int st = kk & 1;
        if (kk + 1 < kiters) {
            load_tile(kk + 1, st ^ 1);
            cp_wait<1>();
        } else {
            cp_wait<0>();
        }
        __syncthreads();

        const float (*Bs2)[72] = sm->Bs[st];
        unsigned stoff = st ? ASTAGE : 0u;

#pragma unroll
        for (int kt = 0; kt < 4; kt++) {
            int kb = kt * 8;
            unsigned a[4][4];
#pragma unroll
            for (int fm = 0; fm < 4; fm++)
                ldsm_x4(a[fm][0], a[fm][1], a[fm][2], a[fm][3],
                        aaddr + stoff + fm * AFM + kb * 4);
#pragma unroll
            for (int fn = 0; fn < 2; fn++) {
                int bcc = wn * 16 + fn * 8 + (lane >> 2);
                int brr = kb + (lane & 3);
                unsigned b0 = ld_tf32(&Bs2[brr][bcc]);
                unsigned b1 = ld_tf32(&Bs2[brr + 4][bcc]);
#pragma unroll
                for (int fm = 0; fm < 4; fm++)
                    mma_tf32(cc[fm][fn], a[fm], b0, b1);
            }
        }
        __syncthreads();
    }

    // epilogue
#pragma unroll
    for (int fm = 0; fm < 4; fm++) {
        int rbase = m0 + wm * 64 + fm * 16 + (lane >> 2);
#pragma unroll
        for (int fn = 0; fn < 2; fn++) {
            int col = n0 + wn * 16 + fn * 8 + (lane & 3) * 2;
#pragma unroll
            for (int half = 0; half < 2; half++) {
                int r = rbase + half * 8;
                if (r >= M) continue;
                float v0 = cc[fm][fn][half * 2 + 0];
                float v1 = cc[fm][fn][half * 2 + 1];
                if (epi == 0) {
                    *reinterpret_cast<float2*>(C + (size_t)r * N + col) =
                        make_float2(v0, v1);
                } else if (epi == 1) {
                    float2 g2 = *reinterpret_cast<const float2*>(
                        G + (size_t)r * N + col);
                    float h0 = rnd_tf32(g2.x / (1.f + expf(-g2.x)) * v0);
                    float h1 = rnd_tf32(g2.y / (1.f + expf(-g2.y)) * v1);
                    *reinterpret_cast<float2*>(C + (size_t)r * N + col) =
                        make_float2(h0, h1);
                } else if (epi == 2) {
                    int dst = slot[r];
                    float s = wts[r];
                    *reinterpret_cast<float2*>(C + (size_t)dst * N + col) =
                        make_float2(s * v0, s * v1);
                } else {
                    *reinterpret_cast<float2*>(C + (size_t)r * N + col) =
                        make_float2(v0, v1);
                }
            }
        }
    }
}

// ---------------- final combine: out += y_tok[2t] + y_tok[2t+1] --------------
__global__ void combine_kernel(float* __restrict__ out) {
    int i = blockIdx.x * blockDim.x + threadIdx.x;
    const int total = T_TOK * HDIM / 4;
    if (i >= total) return;
    int row = i / (HDIM / 4);
    int c4 = i % (HDIM / 4);
    const float4* y0 = reinterpret_cast<const float4*>(d_ytok + (size_t)(2 * row) * HDIM) + c4;
    const float4* y1 = reinterpret_cast<const float4*>(d_ytok + (size_t)(2 * row + 1) * HDIM) + c4;
    float4 o = reinterpret_cast<float4*>(out)[i];
    float4 a = *y0, b = *y1;
    o.x += a.x + b.x; o.y += a.y + b.y;
    o.z += a.z + b.z; o.w += a.w + b.w;
    reinterpret_cast<float4*>(out)[i] = o;
}

// ---------------- launch ------------------------------------------------------
extern "C" void kernel_launch(void* const* d_in, const int* in_sizes, int n_in,
                              void* d_out, int out_size) {
    const float* x     = (const float*)d_in[0];
    const int*   vm    = (const int*)d_in[1];      // bool promoted to int32
    const float* tgate = (const float*)d_in[2];
    const float* twg   = (const float*)d_in[3];
    const float* twu   = (const float*)d_in[4];
    const float* twd   = (const float*)d_in[5];
    const float* igate = (const float*)d_in[6];
    const float* iwg   = (const float*)d_in[7];
    const float* iwu   = (const float*)d_in[8];
    const float* iwd   = (const float*)d_in[9];
    const float* shg   = (const float*)d_in[10];
    const float* shu   = (const float*)d_in[11];
    const float* shd   = (const float*)d_in[12];
    float* out = (float*)d_out;

    const int SMEM = (int)sizeof(GSmem);

    static bool init = false;
    static cudaStream_t s1, s2;
    static cudaEvent_t evRoot, evRoute, evJ1, evJ2;
    if (!init) {
        cudaStreamCreateWithFlags(&s1, cudaStreamNonBlocking);
        cudaStreamCreateWithFlags(&s2, cudaStreamNonBlocking);
        cudaEventCreateWithFlags(&evRoot,  cudaEventDisableTiming);
        cudaEventCreateWithFlags(&evRoute, cudaEventDisableTiming);
        cudaEventCreateWithFlags(&evJ1,    cudaEventDisableTiming);
        cudaEventCreateWithFlags(&evJ2,    cudaEventDisableTiming);
        cudaFuncSetAttribute(gemm_kernel,
            cudaFuncAttributeMaxDynamicSharedMemorySize, SMEM);
        init = true;
    }

    cudaStream_t s0 = 0;   // captured legacy stream

    static float *p_x32 = nullptr, *p_gt, *p_ht, *p_gi, *p_hi, *p_gs, *p_ms, *p_yt;
    if (!p_x32) {
        cudaGetSymbolAddress((void**)&p_x32, d_x32);
        cudaGetSymbolAddress((void**)&p_gt,  d_g_text);
        cudaGetSymbolAddress((void**)&p_ht,  d_h_text);
        cudaGetSymbolAddress((void**)&p_gi,  d_g_img);
        cudaGetSymbolAddress((void**)&p_hi,  d_h_img);
        cudaGetSymbolAddress((void**)&p_gs,  d_g_sh);
        cudaGetSymbolAddress((void**)&p_ms,  d_mid_sh);
        cudaGetSymbolAddress((void**)&p_yt,  d_ytok);
    }

    // prologue on s0
    zero_counts_kernel<<<1, 32, 0, s0>>>();
    {
        int total = T_TOK * HDIM / 4;
        preround_x_kernel<<<(total + 255) / 256, 256, 0, s0>>>(x);
    }
    cudaEventRecord(evRoot, s0);

    // s1: shared chain (independent of routing)
    cudaStreamWaitEvent(s1, evRoot, 0);
    {
        dim3 g(ISH / 64, T_TOK / 128, 1);
        gemm_kernel<<<g, 256, SMEM, s1>>>(p_x32, shg, p_gs, nullptr,
                                          HDIM, ISH, -1, 0, 0, 0, 0);
        gemm_kernel<<<g, 256, SMEM, s1>>>(p_x32, shu, p_ms, p_gs,
                                          HDIM, ISH, -1, 0, 1, 0, 0);
    }
    {
        dim3 g(HDIM / 64, T_TOK / 128, 1);
        gemm_kernel<<<g, 256, SMEM, s1>>>(p_ms, shd, out, nullptr,
                                          ISH, HDIM, -1, 0, 3, 0, 0);
    }
    cudaEventRecord(evJ1, s1);

    // s0: routing
    route_kernel<<<T_TOK, 256, 0, s0>>>(x, vm, tgate, igate);
    cudaEventRecord(evRoute, s0);

    // s2: image chain
    cudaStreamWaitEvent(s2, evRoute, 0);
    {
        dim3 g(IIMG / 64, T_TOK / 128, NEXP);
        gemm_kernel<<<g, 256, SMEM, s2>>>(p_x32, iwg, p_gi, nullptr,
            HDIM, IIMG, 8, 1, 0, 0, (size_t)T_TOK * IIMG);
        gemm_kernel<<<g, 256, SMEM, s2>>>(p_x32, iwu, p_hi, p_gi,
            HDIM, IIMG, 8, 1, 1, 0, (size_t)T_TOK * IIMG);
    }
    {
        dim3 g(HDIM / 64, T_TOK / 128, NEXP);
        gemm_kernel<<<g, 256, SMEM, s2>>>(p_hi, iwd, p_yt, nullptr,
            IIMG, HDIM, 8, 0, 2, (size_t)T_TOK * IIMG, 0);
    }
    cudaEventRecord(evJ2, s2);

    // s0: text chain
    {
        dim3 g(ITXT / 64, T_TOK / 128, NEXP);
        gemm_kernel<<<g, 256, SMEM, s0>>>(p_x32, twg, p_gt, nullptr,
            HDIM, ITXT, 0, 1, 0, 0, (size_t)T_TOK * ITXT);
        gemm_kernel<<<g, 256, SMEM, s0>>>(p_x32, twu, p_ht, p_gt,
            HDIM, ITXT, 0, 1, 1, 0, (size_t)T_TOK * ITXT);
    }
    {
        dim3 g(HDIM / 64, T_TOK / 128, NEXP);
        gemm_kernel<<<g, 256, SMEM, s0>>>(p_ht, twd, p_yt, nullptr,
            ITXT, HDIM, 0, 0, 2, (size_t)T_TOK * ITXT, 0);
    }

    // join + combine
    cudaStreamWaitEvent(s0, evJ1, 0);
    cudaStreamWaitEvent(s0, evJ2, 0);
    {
        int total = T_TOK * HDIM / 4;
        combine_kernel<<<(total + 255) / 256, 256, 0, s0>>>(out);
    }
}

// round 11
// speedup vs baseline: 1.0437x; 1.0437x over previous
#include <cuda_runtime.h>
#include <math.h>

#define T_TOK 2048
#define HDIM  2560
#define NEXP  8
#define ITXT  1536
#define IIMG  512
#define ISH   3072

// ---------------- scratch (static device globals; no allocs allowed) ----------
__device__ int   d_count[16];
__device__ int   d_slot_tok[16][T_TOK];
__device__ float d_slot_wt [16][T_TOK];
__device__ float d_x32 [(size_t)T_TOK * HDIM];            // pre-rounded X (tf32)
__device__ float d_g_text[(size_t)NEXP * T_TOK * ITXT];   // raw G
__device__ float d_h_text[(size_t)NEXP * T_TOK * ITXT];   // h = swiglu
__device__ float d_g_img [(size_t)NEXP * T_TOK * IIMG];
__device__ float d_h_img [(size_t)NEXP * T_TOK * IIMG];
__device__ float d_g_sh  [(size_t)T_TOK * ISH];
__device__ float d_mid_sh[(size_t)T_TOK * ISH];
__device__ float d_ytok  [(size_t)T_TOK * 2 * HDIM];

// ---------------- helpers ----------------------------------------------------
__device__ __forceinline__ unsigned ld_tf32(const float* p) {
    unsigned u;
    asm("cvt.rna.tf32.f32 %0, %1;" : "=r"(u) : "f"(*p));
    return u;
}
__device__ __forceinline__ float rnd_tf32(float x) {
    unsigned u;
    asm("cvt.rna.tf32.f32 %0, %1;" : "=r"(u) : "f"(x));
    return __uint_as_float(u);
}

__device__ __forceinline__ void mma_tf32(float c[4], const unsigned a[4],
                                         unsigned b0, unsigned b1) {
    asm volatile(
        "mma.sync.aligned.m16n8k8.row.col.f32.tf32.tf32.f32 "
        "{%0,%1,%2,%3}, {%4,%5,%6,%7}, {%8,%9}, {%0,%1,%2,%3};"
        : "+f"(c[0]), "+f"(c[1]), "+f"(c[2]), "+f"(c[3])
        : "r"(a[0]), "r"(a[1]), "r"(a[2]), "r"(a[3]), "r"(b0), "r"(b1));
}

__device__ __forceinline__ void ldsm_x4(unsigned& r0, unsigned& r1,
                                        unsigned& r2, unsigned& r3,
                                        unsigned addr) {
    asm volatile("ldmatrix.sync.aligned.m8n8.x4.shared.b16 {%0,%1,%2,%3}, [%4];"
                 : "=r"(r0), "=r"(r1), "=r"(r2), "=r"(r3) : "r"(addr));
}

__device__ __forceinline__ void cp16(void* smem, const void* g, int sz) {
    unsigned s = (unsigned)__cvta_generic_to_shared(smem);
    asm volatile("cp.async.cg.shared.global [%0], [%1], 16, %2;"
                 :: "r"(s), "l"(g), "r"(sz));
}
__device__ __forceinline__ void cp_commit() {
    asm volatile("cp.async.commit_group;");
}
template <int N> __device__ __forceinline__ void cp_wait() {
    asm volatile("cp.async.wait_group %0;" :: "n"(N));
}

// ---------------- init / pre-round -------------------------------------------
__global__ void zero_counts_kernel() {
    if (threadIdx.x < 16) d_count[threadIdx.x] = 0;
}

__global__ void preround_x_kernel(const float* __restrict__ x) {
    int i = blockIdx.x * blockDim.x + threadIdx.x;
    const int total = T_TOK * HDIM / 4;
    if (i >= total) return;
    float4 v = reinterpret_cast<const float4*>(x)[i];
    float4 w;
    w.x = rnd_tf32(v.x); w.y = rnd_tf32(v.y);
    w.z = rnd_tf32(v.z); w.w = rnd_tf32(v.w);
    reinterpret_cast<float4*>(d_x32)[i] = w;
}

// ---------------- routing -----------------------------------------------------
// visual_token_mask: bool in reference -> promoted to int32 by the harness.
__global__ void route_kernel(const float* __restrict__ x,
                             const int* __restrict__ vmask,
                             const float* __restrict__ tgate,
                             const float* __restrict__ igate) {
    int t = blockIdx.x;
    int wid = threadIdx.x >> 5, lane = threadIdx.x & 31;
    bool vis = vmask[t] != 0;
    const float* gw = (vis ? igate : tgate) + (size_t)wid * HDIM;
    const float* xr = x + (size_t)t * HDIM;
    float s = 0.f;
    for (int i = lane; i < HDIM; i += 32) s += xr[i] * gw[i];
#pragma unroll
    for (int o = 16; o; o >>= 1) s += __shfl_xor_sync(0xffffffffu, s, o);
    __shared__ float logit[NEXP];
    if (lane == 0) logit[wid] = s;
    __syncthreads();
    if (threadIdx.x == 0) {
        float mx = logit[0];
#pragma unroll
        for (int e = 1; e < NEXP; e++) mx = fmaxf(mx, logit[e]);
        float p[NEXP];
#pragma unroll
        for (int e = 0; e < NEXP; e++) p[e] = expf(logit[e] - mx);
        int i0 = 0;
#pragma unroll
        for (int e = 1; e < NEXP; e++) if (p[e] > p[i0]) i0 = e;
        int i1 = (i0 == 0) ? 1 : 0;
#pragma unroll
        for (int e = 0; e < NEXP; e++)
            if (e != i0 && p[e] > p[i1]) i1 = e;
        float denom = p[i0] + p[i1];
        float w0 = p[i0] / denom;
        float w1 = p[i1] / denom;
        int base = vis ? 8 : 0;
        int g0 = base + i0;
        int g1 = base + i1;
        int pos0 = atomicAdd(&d_count[g0], 1);
        d_slot_tok[g0][pos0] = t * 2 + 0;
        d_slot_wt [g0][pos0] = w0;
        int pos1 = atomicAdd(&d_count[g1], 1);
        d_slot_tok[g1][pos1] = t * 2 + 1;
        d_slot_wt [g1][pos1] = w1;
    }
}

// ---------------- unified GEMM ------------------------------------------------
// C[128x64] per CTA, BK=32, 2-stage cp.async, 8 warps 4(m) x 2(n),
// warp tile 32x32; kt-loop register double-buffering of A/B fragments.
// epi: 0 = store raw, 1 = swiglu (h = rnd(silu(g)*u)), 2 = scatter+scale,
//      3 = direct store.
struct GSmem {
    float As[2][128][36];
    float Bs[2][32][72];
    int   srcs[128];
};

__global__ __launch_bounds__(256, 3)
void gemm_kernel(const float* __restrict__ A_base,
                 const float* __restrict__ B_base,
                 float* __restrict__ C_base,
                 const float* __restrict__ G_base,
                 int K, int N, int sgbase, int a_gather, int epi,
                 size_t a_estride, size_t c_estride) {
    extern __shared__ char smem_raw[];
    GSmem* sm = reinterpret_cast<GSmem*>(smem_raw);

    int e = blockIdx.z;
    const int* slot = nullptr;
    const float* wts = nullptr;
    int M;
    if (sgbase >= 0) {
        M = d_count[sgbase + e];
        slot = d_slot_tok[sgbase + e];
        wts  = d_slot_wt [sgbase + e];
    } else {
        M = T_TOK;
    }
    int m0 = blockIdx.y * 128;
    if (m0 >= M) return;
    int n0 = blockIdx.x * 64;

    const float* A = A_base + (size_t)e * a_estride;
    const float* B = B_base + (size_t)e * K * N;
    float* C = C_base + (size_t)e * c_estride;
    const float* G = G_base ? G_base + (size_t)e * c_estride : nullptr;

    int tid = threadIdx.x;
    if (tid < 128) {
        int gr = m0 + tid;
        int s = -1;
        if (gr < M) s = (a_gather && slot) ? (slot[gr] >> 1) : gr;
        sm->srcs[tid] = s;
    }
    __syncthreads();

    int warp = tid >> 5, lane = tid & 31;
    int wm = warp >> 1, wn = warp & 1;     // 4 x 2 warp grid (R9 geometry)
    int ar = tid >> 3;            // A loader rows 0..31 (stride 32)
    int ac = (tid & 7) * 4;
    int bkr = tid >> 4;           // B loader k-rows 0..15 (stride 16)
    int bc  = (tid & 15) * 4;

    int asrc[4];
#pragma unroll
    for (int j = 0; j < 4; j++) asrc[j] = sm->srcs[ar + j * 32];

    // ldmatrix addresses: per fm one x4 covering rows {0-7,8-15} x cols {kb,kb+4}
    unsigned As0 = (unsigned)__cvta_generic_to_shared(&sm->As[0][0][0]);
    int arow = wm * 32 + (lane & 7) + ((lane >> 3) & 1) * 8;
    int acol = (lane >> 4) * 4;
    unsigned aaddr0 = As0 + (unsigned)((arow * 36 + acol) * 4);
    unsigned aaddr1 = aaddr0 + 16u * 36u * 4u;
    const unsigned ASTAGE = 128u * 36u * 4u;

    // B fragment indices (constant across kt)
    int bcc0 = wn * 32 + 0 * 8 + (lane >> 2);
    int blr  = lane & 3;

    float cc[2][4][4];
#pragma unroll
    for (int a = 0; a < 2; a++)
#pragma unroll
        for (int b = 0; b < 4; b++)
#pragma unroll
            for (int c = 0; c < 4; c++) cc[a][b][c] = 0.f;

    auto load_tile = [&](int kk, int st) {
        int k0 = kk * 32;
#pragma unroll
        for (int j = 0; j < 4; j++) {
            int r = ar + j * 32;
            int s = asrc[j];
            cp16(&sm->As[st][r][ac],
                 A + (size_t)(s >= 0 ? s : 0) * K + k0 + ac,
                 s >= 0 ? 16 : 0);
        }
#pragma unroll
        for (int j = 0; j < 2; j++) {
            int kr = bkr + j * 16;
            cp16(&sm->Bs[st][kr][bc], B + (size_t)(k0 + kr) * N + n0 + bc, 16);
        }
        cp_commit();
    };

    int kiters = K >> 5;
    load_tile(0, 0);

    for (int kk = 0; kk < kiters; kk++) {
        int st = kk & 1;
        if (kk + 1 < kiters) {
            load_tile(kk + 1, st ^ 1);
            cp_wait<1>();
        } else {
            cp_wait<0>();
        }
        __syncthreads();

        const float (*Bs2)[72] = sm->Bs[st];
        unsigned stoff = st ? ASTAGE : 0u;

        // register-pipelined kt loop: prefetch kt+1 fragments during kt MMAs
        unsigned a[2][2][4];       // [buf][fm][frag]
        unsigned bf[2][4][2];      // [buf][fn][b0/b1]

        // preload kt = 0
        ldsm_x4(a[0][0][0], a[0][0][1], a[0][0][2], a[0][0][3], aaddr0 + stoff);
        ldsm_x4(a[0][1][0], a[0][1][1], a[0][1][2], a[0][1][3], aaddr1 + stoff);
#pragma unroll
        for (int fn = 0; fn < 4; fn++) {
            int bcc = bcc0 + fn * 8;
            bf[0][fn][0] = ld_tf32(&Bs2[blr][bcc]);
            bf[0][fn][1] = ld_tf32(&Bs2[blr + 4][bcc]);
        }

#pragma unroll
        for (int kt = 0; kt < 4; kt++) {
            int cur = kt & 1, nxt = cur ^ 1;
            if (kt < 3) {
                int kbn = (kt + 1) * 8;
                ldsm_x4(a[nxt][0][0], a[nxt][0][1], a[nxt][0][2], a[nxt][0][3],
                        aaddr0 + stoff + kbn * 4);
                ldsm_x4(a[nxt][1][0], a[nxt][1][1], a[nxt][1][2], a[nxt][1][3],
                        aaddr1 + stoff + kbn * 4);
#pragma unroll
                for (int fn = 0; fn < 4; fn++) {
                    int bcc = bcc0 + fn * 8;
                    bf[nxt][fn][0] = ld_tf32(&Bs2[kbn + blr][bcc]);
                    bf[nxt][fn][1] = ld_tf32(&Bs2[kbn + blr + 4][bcc]);
                }
            }
#pragma unroll
            for (int fn = 0; fn < 4; fn++) {
                mma_tf32(cc[0][fn], a[cur][0], bf[cur][fn][0], bf[cur][fn][1]);
                mma_tf32(cc[1][fn], a[cur][1], bf[cur][fn][0], bf[cur][fn][1]);
            }
        }
        __syncthreads();
    }

    // epilogue
#pragma unroll
    for (int fm = 0; fm < 2; fm++) {
        int rbase = m0 + wm * 32 + fm * 16 + (lane >> 2);
#pragma unroll
        for (int fn = 0; fn < 4; fn++) {
            int col = n0 + wn * 32 + fn * 8 + (lane & 3) * 2;
#pragma unroll
            for (int half = 0; half < 2; half++) {
                int r = rbase + half * 8;
                if (r >= M) continue;
                float v0 = cc[fm][fn][half * 2 + 0];
                float v1 = cc[fm][fn][half * 2 + 1];
                if (epi == 0) {
                    *reinterpret_cast<float2*>(C + (size_t)r * N + col) =
                        make_float2(v0, v1);
                } else if (epi == 1) {
                    float2 g2 = *reinterpret_cast<const float2*>(
                        G + (size_t)r * N + col);
                    float h0 = rnd_tf32(g2.x / (1.f + expf(-g2.x)) * v0);
                    float h1 = rnd_tf32(g2.y / (1.f + expf(-g2.y)) * v1);
                    *reinterpret_cast<float2*>(C + (size_t)r * N + col) =
                        make_float2(h0, h1);
                } else if (epi == 2) {
                    int dst = slot[r];
                    float s = wts[r];
                    *reinterpret_cast<float2*>(C + (size_t)dst * N + col) =
                        make_float2(s * v0, s * v1);
                } else {
                    *reinterpret_cast<float2*>(C + (size_t)r * N + col) =
                        make_float2(v0, v1);
                }
            }
        }
    }
}

// ---------------- final combine: out += y_tok[2t] + y_tok[2t+1] --------------
__global__ void combine_kernel(float* __restrict__ out) {
    int i = blockIdx.x * blockDim.x + threadIdx.x;
    const int total = T_TOK * HDIM / 4;
    if (i >= total) return;
    int row = i / (HDIM / 4);
    int c4 = i % (HDIM / 4);
    const float4* y0 = reinterpret_cast<const float4*>(d_ytok + (size_t)(2 * row) * HDIM) + c4;
    const float4* y1 = reinterpret_cast<const float4*>(d_ytok + (size_t)(2 * row + 1) * HDIM) + c4;
    float4 o = reinterpret_cast<float4*>(out)[i];
    float4 a = *y0, b = *y1;
    o.x += a.x + b.x; o.y += a.y + b.y;
    o.z += a.z + b.z; o.w += a.w + b.w;
    reinterpret_cast<float4*>(out)[i] = o;
}

// ---------------- launch ------------------------------------------------------
extern "C" void kernel_launch(void* const* d_in, const int* in_sizes, int n_in,
                              void* d_out, int out_size) {
    const float* x     = (const float*)d_in[0];
    const int*   vm    = (const int*)d_in[1];      // bool promoted to int32
    const float* tgate = (const float*)d_in[2];
    const float* twg   = (const float*)d_in[3];
    const float* twu   = (const float*)d_in[4];
    const float* twd   = (const float*)d_in[5];
    const float* igate = (const float*)d_in[6];
    const float* iwg   = (const float*)d_in[7];
    const float* iwu   = (const float*)d_in[8];
    const float* iwd   = (const float*)d_in[9];
    const float* shg   = (const float*)d_in[10];
    const float* shu   = (const float*)d_in[11];
    const float* shd   = (const float*)d_in[12];
    float* out = (float*)d_out;

    const int SMEM = (int)sizeof(GSmem);

    static bool init = false;
    static cudaStream_t s1, s2;
    static cudaEvent_t evRoot, evRoute, evJ1, evJ2;
    if (!init) {
        cudaStreamCreateWithFlags(&s1, cudaStreamNonBlocking);
        cudaStreamCreateWithFlags(&s2, cudaStreamNonBlocking);
        cudaEventCreateWithFlags(&evRoot,  cudaEventDisableTiming);
        cudaEventCreateWithFlags(&evRoute, cudaEventDisableTiming);
        cudaEventCreateWithFlags(&evJ1,    cudaEventDisableTiming);
        cudaEventCreateWithFlags(&evJ2,    cudaEventDisableTiming);
        cudaFuncSetAttribute(gemm_kernel,
            cudaFuncAttributeMaxDynamicSharedMemorySize, SMEM);
        init = true;
    }

    cudaStream_t s0 = 0;   // captured legacy stream

    static float *p_x32 = nullptr, *p_gt, *p_ht, *p_gi, *p_hi, *p_gs, *p_ms, *p_yt;
    if (!p_x32) {
        cudaGetSymbolAddress((void**)&p_x32, d_x32);
        cudaGetSymbolAddress((void**)&p_gt,  d_g_text);
        cudaGetSymbolAddress((void**)&p_ht,  d_h_text);
        cudaGetSymbolAddress((void**)&p_gi,  d_g_img);
        cudaGetSymbolAddress((void**)&p_hi,  d_h_img);
        cudaGetSymbolAddress((void**)&p_gs,  d_g_sh);
        cudaGetSymbolAddress((void**)&p_ms,  d_mid_sh);
        cudaGetSymbolAddress((void**)&p_yt,  d_ytok);
    }

    // prologue on s0
    zero_counts_kernel<<<1, 32, 0, s0>>>();
    {
        int total = T_TOK * HDIM / 4;
        preround_x_kernel<<<(total + 255) / 256, 256, 0, s0>>>(x);
    }
    cudaEventRecord(evRoot, s0);

    // s1: shared chain (independent of routing)
    cudaStreamWaitEvent(s1, evRoot, 0);
    {
        dim3 g(ISH / 64, T_TOK / 128, 1);
        gemm_kernel<<<g, 256, SMEM, s1>>>(p_x32, shg, p_gs, nullptr,
                                          HDIM, ISH, -1, 0, 0, 0, 0);
        gemm_kernel<<<g, 256, SMEM, s1>>>(p_x32, shu, p_ms, p_gs,
                                          HDIM, ISH, -1, 0, 1, 0, 0);
    }
    {
        dim3 g(HDIM / 64, T_TOK / 128, 1);
        gemm_kernel<<<g, 256, SMEM, s1>>>(p_ms, shd, out, nullptr,
                                          ISH, HDIM, -1, 0, 3, 0, 0);
    }
    cudaEventRecord(evJ1, s1);

    // s0: routing
    route_kernel<<<T_TOK, 256, 0, s0>>>(x, vm, tgate, igate);
    cudaEventRecord(evRoute, s0);

    // s2: image chain
    cudaStreamWaitEvent(s2, evRoute, 0);
    {
        dim3 g(IIMG / 64, T_TOK / 128, NEXP);
        gemm_kernel<<<g, 256, SMEM, s2>>>(p_x32, iwg, p_gi, nullptr,
            HDIM, IIMG, 8, 1, 0, 0, (size_t)T_TOK * IIMG);
        gemm_kernel<<<g, 256, SMEM, s2>>>(p_x32, iwu, p_hi, p_gi,
            HDIM, IIMG, 8, 1, 1, 0, (size_t)T_TOK * IIMG);
    }
    {
        dim3 g(HDIM / 64, T_TOK / 128, NEXP);
        gemm_kernel<<<g, 256, SMEM, s2>>>(p_hi, iwd, p_yt, nullptr,
            IIMG, HDIM, 8, 0, 2, (size_t)T_TOK * IIMG, 0);
    }
    cudaEventRecord(evJ2, s2);

    // s0: text chain
    {
        dim3 g(ITXT / 64, T_TOK / 128, NEXP);
        gemm_kernel<<<g, 256, SMEM, s0>>>(p_x32, twg, p_gt, nullptr,
            HDIM, ITXT, 0, 1, 0, 0, (size_t)T_TOK * ITXT);
        gemm_kernel<<<g, 256, SMEM, s0>>>(p_x32, twu, p_ht, p_gt,
            HDIM, ITXT, 0, 1, 1, 0, (size_t)T_TOK * ITXT);
    }
    {
        dim3 g(HDIM / 64, T_TOK / 128, NEXP);
        gemm_kernel<<<g, 256, SMEM, s0>>>(p_ht, twd, p_yt, nullptr,
            ITXT, HDIM, 0, 0, 2, (size_t)T_TOK * ITXT, 0);
    }

    // join + combine
    cudaStreamWaitEvent(s0, evJ1, 0);
    cudaStreamWaitEvent(s0, evJ2, 0);
    {
        int total = T_TOK * HDIM / 4;
        combine_kernel<<<(total + 255) / 256, 256, 0, s0>>>(out);
    }
}

// round 12
// speedup vs baseline: 1.0745x; 1.0295x over previous
#include <cuda_runtime.h>
#include <math.h>

#define T_TOK 2048
#define HDIM  2560
#define NEXP  8
#define ITXT  1536
#define IIMG  512
#define ISH   3072

// ---------------- scratch (static device globals; no allocs allowed) ----------
__device__ int   d_count[16];
__device__ int   d_slot_tok[16][T_TOK];
__device__ float d_slot_wt [16][T_TOK];
__device__ float d_x32 [(size_t)T_TOK * HDIM];            // pre-rounded X (tf32)
__device__ float d_h_text[(size_t)NEXP * T_TOK * ITXT];   // h = swiglu
__device__ float d_h_img [(size_t)NEXP * T_TOK * IIMG];
__device__ float d_mid_sh[(size_t)T_TOK * ISH];
__device__ float d_ytok  [(size_t)T_TOK * 2 * HDIM];

// ---------------- helpers ----------------------------------------------------
__device__ __forceinline__ unsigned ld_tf32(const float* p) {
    unsigned u;
    asm("cvt.rna.tf32.f32 %0, %1;" : "=r"(u) : "f"(*p));
    return u;
}
__device__ __forceinline__ float rnd_tf32(float x) {
    unsigned u;
    asm("cvt.rna.tf32.f32 %0, %1;" : "=r"(u) : "f"(x));
    return __uint_as_float(u);
}

__device__ __forceinline__ void mma_tf32(float c[4], const unsigned a[4],
                                         unsigned b0, unsigned b1) {
    asm volatile(
        "mma.sync.aligned.m16n8k8.row.col.f32.tf32.tf32.f32 "
        "{%0,%1,%2,%3}, {%4,%5,%6,%7}, {%8,%9}, {%0,%1,%2,%3};"
        : "+f"(c[0]), "+f"(c[1]), "+f"(c[2]), "+f"(c[3])
        : "r"(a[0]), "r"(a[1]), "r"(a[2]), "r"(a[3]), "r"(b0), "r"(b1));
}

__device__ __forceinline__ void ldsm_x4(unsigned& r0, unsigned& r1,
                                        unsigned& r2, unsigned& r3,
                                        unsigned addr) {
    asm volatile("ldmatrix.sync.aligned.m8n8.x4.shared.b16 {%0,%1,%2,%3}, [%4];"
                 : "=r"(r0), "=r"(r1), "=r"(r2), "=r"(r3) : "r"(addr));
}

__device__ __forceinline__ void cp16(void* smem, const void* g, int sz) {
    unsigned s = (unsigned)__cvta_generic_to_shared(smem);
    asm volatile("cp.async.cg.shared.global [%0], [%1], 16, %2;"
                 :: "r"(s), "l"(g), "r"(sz));
}
__device__ __forceinline__ void cp_commit() {
    asm volatile("cp.async.commit_group;");
}
template <int N> __device__ __forceinline__ void cp_wait() {
    asm volatile("cp.async.wait_group %0;" :: "n"(N));
}

// ---------------- init / pre-round -------------------------------------------
__global__ void zero_counts_kernel() {
    if (threadIdx.x < 16) d_count[threadIdx.x] = 0;
}

__global__ void preround_x_kernel(const float* __restrict__ x) {
    int i = blockIdx.x * blockDim.x + threadIdx.x;
    const int total = T_TOK * HDIM / 4;
    if (i >= total) return;
    float4 v = reinterpret_cast<const float4*>(x)[i];
    float4 w;
    w.x = rnd_tf32(v.x); w.y = rnd_tf32(v.y);
    w.z = rnd_tf32(v.z); w.w = rnd_tf32(v.w);
    reinterpret_cast<float4*>(d_x32)[i] = w;
}

// ---------------- routing -----------------------------------------------------
// visual_token_mask: bool in reference -> promoted to int32 by the harness.
__global__ void route_kernel(const float* __restrict__ x,
                             const int* __restrict__ vmask,
                             const float* __restrict__ tgate,
                             const float* __restrict__ igate) {
    int t = blockIdx.x;
    int wid = threadIdx.x >> 5, lane = threadIdx.x & 31;
    bool vis = vmask[t] != 0;
    const float* gw = (vis ? igate : tgate) + (size_t)wid * HDIM;
    const float* xr = x + (size_t)t * HDIM;
    float s = 0.f;
    for (int i = lane; i < HDIM; i += 32) s += xr[i] * gw[i];
#pragma unroll
    for (int o = 16; o; o >>= 1) s += __shfl_xor_sync(0xffffffffu, s, o);
    __shared__ float logit[NEXP];
    if (lane == 0) logit[wid] = s;
    __syncthreads();
    if (threadIdx.x == 0) {
        float mx = logit[0];
#pragma unroll
        for (int e = 1; e < NEXP; e++) mx = fmaxf(mx, logit[e]);
        float p[NEXP];
#pragma unroll
        for (int e = 0; e < NEXP; e++) p[e] = expf(logit[e] - mx);
        int i0 = 0;
#pragma unroll
        for (int e = 1; e < NEXP; e++) if (p[e] > p[i0]) i0 = e;
        int i1 = (i0 == 0) ? 1 : 0;
#pragma unroll
        for (int e = 0; e < NEXP; e++)
            if (e != i0 && p[e] > p[i1]) i1 = e;
        float denom = p[i0] + p[i1];
        float w0 = p[i0] / denom;
        float w1 = p[i1] / denom;
        int base = vis ? 8 : 0;
        int g0 = base + i0;
        int g1 = base + i1;
        int pos0 = atomicAdd(&d_count[g0], 1);
        d_slot_tok[g0][pos0] = t * 2 + 0;
        d_slot_wt [g0][pos0] = w0;
        int pos1 = atomicAdd(&d_count[g1], 1);
        d_slot_tok[g1][pos1] = t * 2 + 1;
        d_slot_wt [g1][pos1] = w1;
    }
}

// ---------------- fused up-projection (dual GEMM + SwiGLU) --------------------
// C tile 128x64, BK=32, 2-stage cp.async, 8 warps 4(m) x 2(n), warp 32x32.
// G and U share the A tile and barriers: 128 MMAs per warp-ktile.
// A = d_x32 (pre-rounded). sgbase: -1 -> dense (M=T_TOK); else slot group.
struct UpSmem {
    float As[2][128][36];
    float Bg[2][32][72];
    float Bu[2][32][72];
    int   srcs[128];
};

__global__ __launch_bounds__(256, 2)
void up_fused(const float* __restrict__ Wg_base,
              const float* __restrict__ Wu_base,
              float* __restrict__ H_base,
              int K, int N, int sgbase,
              size_t c_estride) {
    extern __shared__ char smem_raw[];
    UpSmem* sm = reinterpret_cast<UpSmem*>(smem_raw);

    int e = blockIdx.z;
    const int* slot = nullptr;
    int M;
    if (sgbase >= 0) { M = d_count[sgbase + e]; slot = d_slot_tok[sgbase + e]; }
    else             { M = T_TOK; }
    int m0 = blockIdx.y * 128;
    if (m0 >= M) return;
    int n0 = blockIdx.x * 64;

    const float* X  = d_x32;
    const float* Wg = Wg_base + (size_t)e * K * N;
    const float* Wu = Wu_base + (size_t)e * K * N;
    float* H = H_base + (size_t)e * c_estride;

    int tid = threadIdx.x;
    if (tid < 128) {
        int gr = m0 + tid;
        int s = -1;
        if (gr < M) s = slot ? (slot[gr] >> 1) : gr;
        sm->srcs[tid] = s;
    }
    __syncthreads();

    int warp = tid >> 5, lane = tid & 31;
    int wm = warp >> 1, wn = warp & 1;
    int ar = tid >> 3;
    int ac = (tid & 7) * 4;
    int bkr = tid >> 4;
    int bc  = (tid & 15) * 4;

    int asrc[4];
#pragma unroll
    for (int j = 0; j < 4; j++) asrc[j] = sm->srcs[ar + j * 32];

    unsigned As0 = (unsigned)__cvta_generic_to_shared(&sm->As[0][0][0]);
    int arow = wm * 32 + (lane & 7) + ((lane >> 3) & 1) * 8;
    int acol = (lane >> 4) * 4;
    unsigned aaddr0 = As0 + (unsigned)((arow * 36 + acol) * 4);
    unsigned aaddr1 = aaddr0 + 16u * 36u * 4u;
    const unsigned ASTAGE = 128u * 36u * 4u;

    float cg[2][4][4];
    float cu[2][4][4];
#pragma unroll
    for (int a = 0; a < 2; a++)
#pragma unroll
        for (int b = 0; b < 4; b++)
#pragma unroll
            for (int c = 0; c < 4; c++) { cg[a][b][c] = 0.f; cu[a][b][c] = 0.f; }

    auto load_tile = [&](int kk, int st) {
        int k0 = kk * 32;
#pragma unroll
        for (int j = 0; j < 4; j++) {
            int r = ar + j * 32;
            int s = asrc[j];
            cp16(&sm->As[st][r][ac],
                 X + (size_t)(s >= 0 ? s : 0) * K + k0 + ac,
                 s >= 0 ? 16 : 0);
        }
#pragma unroll
        for (int j = 0; j < 2; j++) {
            int kr = bkr + j * 16;
            cp16(&sm->Bg[st][kr][bc], Wg + (size_t)(k0 + kr) * N + n0 + bc, 16);
            cp16(&sm->Bu[st][kr][bc], Wu + (size_t)(k0 + kr) * N + n0 + bc, 16);
        }
        cp_commit();
    };

    int kiters = K >> 5;
    load_tile(0, 0);

    for (int kk = 0; kk < kiters; kk++) {
        int st = kk & 1;
        if (kk + 1 < kiters) {
            load_tile(kk + 1, st ^ 1);
            cp_wait<1>();
        } else {
            cp_wait<0>();
        }
        __syncthreads();

        const float (*Bg2)[72] = sm->Bg[st];
        const float (*Bu2)[72] = sm->Bu[st];
        unsigned stoff = st ? ASTAGE : 0u;

#pragma unroll
        for (int kt = 0; kt < 4; kt++) {
            int kb = kt * 8;
            unsigned a[2][4];
            ldsm_x4(a[0][0], a[0][1], a[0][2], a[0][3], aaddr0 + stoff + kb * 4);
            ldsm_x4(a[1][0], a[1][1], a[1][2], a[1][3], aaddr1 + stoff + kb * 4);
#pragma unroll
            for (int fn = 0; fn < 4; fn++) {
                int bcc = wn * 32 + fn * 8 + (lane >> 2);
                int brr = kb + (lane & 3);
                unsigned bg0 = ld_tf32(&Bg2[brr][bcc]);
                unsigned bg1 = ld_tf32(&Bg2[brr + 4][bcc]);
                unsigned bu0 = ld_tf32(&Bu2[brr][bcc]);
                unsigned bu1 = ld_tf32(&Bu2[brr + 4][bcc]);
                mma_tf32(cg[0][fn], a[0], bg0, bg1);
                mma_tf32(cg[1][fn], a[1], bg0, bg1);
                mma_tf32(cu[0][fn], a[0], bu0, bu1);
                mma_tf32(cu[1][fn], a[1], bu0, bu1);
            }
        }
        __syncthreads();
    }

    // epilogue: h = rnd_tf32(silu(g) * u)
#pragma unroll
    for (int fm = 0; fm < 2; fm++) {
        int rbase = m0 + wm * 32 + fm * 16 + (lane >> 2);
#pragma unroll
        for (int fn = 0; fn < 4; fn++) {
            int col = n0 + wn * 32 + fn * 8 + (lane & 3) * 2;
#pragma unroll
            for (int half = 0; half < 2; half++) {
                int r = rbase + half * 8;
                if (r >= M) continue;
                float g0 = cg[fm][fn][half * 2 + 0];
                float g1 = cg[fm][fn][half * 2 + 1];
                float u0 = cu[fm][fn][half * 2 + 0];
                float u1 = cu[fm][fn][half * 2 + 1];
                float h0 = rnd_tf32(g0 / (1.f + expf(-g0)) * u0);
                float h1 = rnd_tf32(g1 / (1.f + expf(-g1)) * u1);
                *reinterpret_cast<float2*>(H + (size_t)r * N + col) =
                    make_float2(h0, h1);
            }
        }
    }
}

// ---------------- down-projection (R9 geometry, best known) -------------------
// epi: 2 = scatter+scale into y_tok, 3 = direct store.
struct GSmem {
    float As[2][128][36];
    float Bs[2][32][72];
};

__global__ __launch_bounds__(256, 3)
void down_gemm(const float* __restrict__ A_base,
               const float* __restrict__ B_base,
               float* __restrict__ C_base,
               int K, int N, int sgbase, int epi,
               size_t a_estride) {
    extern __shared__ char smem_raw[];
    GSmem* sm = reinterpret_cast<GSmem*>(smem_raw);

    int e = blockIdx.z;
    const int* slot = nullptr;
    const float* wts = nullptr;
    int M;
    if (sgbase >= 0) {
        M = d_count[sgbase + e];
        slot = d_slot_tok[sgbase + e];
        wts  = d_slot_wt [sgbase + e];
    } else {
        M = T_TOK;
    }
    int m0 = blockIdx.y * 128;
    if (m0 >= M) return;
    int n0 = blockIdx.x * 64;

    const float* A = A_base + (size_t)e * a_estride;
    const float* B = B_base + (size_t)e * K * N;
    float* C = C_base;

    int tid = threadIdx.x;
    int warp = tid >> 5, lane = tid & 31;
    int wm = warp >> 1, wn = warp & 1;
    int ar = tid >> 3;
    int ac = (tid & 7) * 4;
    int bkr = tid >> 4;
    int bc  = (tid & 15) * 4;

    unsigned As0 = (unsigned)__cvta_generic_to_shared(&sm->As[0][0][0]);
    int arow = wm * 32 + (lane & 7) + ((lane >> 3) & 1) * 8;
    int acol = (lane >> 4) * 4;
    unsigned aaddr0 = As0 + (unsigned)((arow * 36 + acol) * 4);
    unsigned aaddr1 = aaddr0 + 16u * 36u * 4u;
    const unsigned ASTAGE = 128u * 36u * 4u;

    float cc[2][4][4];
#pragma unroll
    for (int a = 0; a < 2; a++)
#pragma unroll
        for (int b = 0; b < 4; b++)
#pragma unroll
            for (int c = 0; c < 4; c++) cc[a][b][c] = 0.f;

    auto load_tile = [&](int kk, int st) {
        int k0 = kk * 32;
#pragma unroll
        for (int j = 0; j < 4; j++) {
            int r = ar + j * 32;
            int gr = m0 + r;
            cp16(&sm->As[st][r][ac],
                 A + (size_t)(gr < M ? gr : 0) * K + k0 + ac,
                 gr < M ? 16 : 0);
        }
#pragma unroll
        for (int j = 0; j < 2; j++) {
            int kr = bkr + j * 16;
            cp16(&sm->Bs[st][kr][bc], B + (size_t)(k0 + kr) * N + n0 + bc, 16);
        }
        cp_commit();
    };

    int kiters = K >> 5;
    load_tile(0, 0);

    for (int kk = 0; kk < kiters; kk++) {
        int st = kk & 1;
        if (kk + 1 < kiters) {
            load_tile(kk + 1, st ^ 1);
            cp_wait<1>();
        } else {
            cp_wait<0>();
        }
        __syncthreads();

        const float (*Bs2)[72] = sm->Bs[st];
        unsigned stoff = st ? ASTAGE : 0u;

#pragma unroll
        for (int kt = 0; kt < 4; kt++) {
            int kb = kt * 8;
            unsigned a[2][4];
            ldsm_x4(a[0][0], a[0][1], a[0][2], a[0][3], aaddr0 + stoff + kb * 4);
            ldsm_x4(a[1][0], a[1][1], a[1][2], a[1][3], aaddr1 + stoff + kb * 4);
#pragma unroll
            for (int fn = 0; fn < 4; fn++) {
                int bcc = wn * 32 + fn * 8 + (lane >> 2);
                int brr = kb + (lane & 3);
                unsigned b0 = ld_tf32(&Bs2[brr][bcc]);
                unsigned b1 = ld_tf32(&Bs2[brr + 4][bcc]);
                mma_tf32(cc[0][fn], a[0], b0, b1);
                mma_tf32(cc[1][fn], a[1], b0, b1);
            }
        }
        __syncthreads();
    }

#pragma unroll
    for (int fm = 0; fm < 2; fm++) {
        int rbase = m0 + wm * 32 + fm * 16 + (lane >> 2);
#pragma unroll
        for (int fn = 0; fn < 4; fn++) {
            int col = n0 + wn * 32 + fn * 8 + (lane & 3) * 2;
#pragma unroll
            for (int half = 0; half < 2; half++) {
                int r = rbase + half * 8;
                if (r >= M) continue;
                float v0 = cc[fm][fn][half * 2 + 0];
                float v1 = cc[fm][fn][half * 2 + 1];
                if (epi == 2) {
                    int dst = slot[r];
                    float s = wts[r];
                    *reinterpret_cast<float2*>(C + (size_t)dst * N + col) =
                        make_float2(s * v0, s * v1);
                } else {
                    *reinterpret_cast<float2*>(C + (size_t)r * N + col) =
                        make_float2(v0, v1);
                }
            }
        }
    }
}

// ---------------- final combine: out += y_tok[2t] + y_tok[2t+1] --------------
__global__ void combine_kernel(float* __restrict__ out) {
    int i = blockIdx.x * blockDim.x + threadIdx.x;
    const int total = T_TOK * HDIM / 4;
    if (i >= total) return;
    int row = i / (HDIM / 4);
    int c4 = i % (HDIM / 4);
    const float4* y0 = reinterpret_cast<const float4*>(d_ytok + (size_t)(2 * row) * HDIM) + c4;
    const float4* y1 = reinterpret_cast<const float4*>(d_ytok + (size_t)(2 * row + 1) * HDIM) + c4;
    float4 o = reinterpret_cast<float4*>(out)[i];
    float4 a = *y0, b = *y1;
    o.x += a.x + b.x; o.y += a.y + b.y;
    o.z += a.z + b.z; o.w += a.w + b.w;
    reinterpret_cast<float4*>(out)[i] = o;
}

// ---------------- launch ------------------------------------------------------
extern "C" void kernel_launch(void* const* d_in, const int* in_sizes, int n_in,
                              void* d_out, int out_size) {
    const float* x     = (const float*)d_in[0];
    const int*   vm    = (const int*)d_in[1];      // bool promoted to int32
    const float* tgate = (const float*)d_in[2];
    const float* twg   = (const float*)d_in[3];
    const float* twu   = (const float*)d_in[4];
    const float* twd   = (const float*)d_in[5];
    const float* igate = (const float*)d_in[6];
    const float* iwg   = (const float*)d_in[7];
    const float* iwu   = (const float*)d_in[8];
    const float* iwd   = (const float*)d_in[9];
    const float* shg   = (const float*)d_in[10];
    const float* shu   = (const float*)d_in[11];
    const float* shd   = (const float*)d_in[12];
    float* out = (float*)d_out;

    const int UP_SMEM   = (int)sizeof(UpSmem);
    const int DOWN_SMEM = (int)sizeof(GSmem);

    static bool init = false;
    static cudaStream_t s1, s2;
    static cudaEvent_t evRoot, evRoute, evJ1, evJ2;
    if (!init) {
        cudaStreamCreateWithFlags(&s1, cudaStreamNonBlocking);
        cudaStreamCreateWithFlags(&s2, cudaStreamNonBlocking);
        cudaEventCreateWithFlags(&evRoot,  cudaEventDisableTiming);
        cudaEventCreateWithFlags(&evRoute, cudaEventDisableTiming);
        cudaEventCreateWithFlags(&evJ1,    cudaEventDisableTiming);
        cudaEventCreateWithFlags(&evJ2,    cudaEventDisableTiming);
        cudaFuncSetAttribute(up_fused,
            cudaFuncAttributeMaxDynamicSharedMemorySize, UP_SMEM);
        cudaFuncSetAttribute(down_gemm,
            cudaFuncAttributeMaxDynamicSharedMemorySize, DOWN_SMEM);
        init = true;
    }

    cudaStream_t s0 = 0;   // captured legacy stream

    static float *p_x32 = nullptr, *p_ht, *p_hi, *p_ms, *p_yt;
    if (!p_x32) {
        cudaGetSymbolAddress((void**)&p_x32, d_x32);
        cudaGetSymbolAddress((void**)&p_ht,  d_h_text);
        cudaGetSymbolAddress((void**)&p_hi,  d_h_img);
        cudaGetSymbolAddress((void**)&p_ms,  d_mid_sh);
        cudaGetSymbolAddress((void**)&p_yt,  d_ytok);
    }

    // prologue on s0
    zero_counts_kernel<<<1, 32, 0, s0>>>();
    {
        int total = T_TOK * HDIM / 4;
        preround_x_kernel<<<(total + 255) / 256, 256, 0, s0>>>(x);
    }
    cudaEventRecord(evRoot, s0);

    // s1: shared chain (independent of routing)
    cudaStreamWaitEvent(s1, evRoot, 0);
    {
        dim3 g(ISH / 64, T_TOK / 128, 1);
        up_fused<<<g, 256, UP_SMEM, s1>>>(shg, shu, p_ms, HDIM, ISH, -1, 0);
    }
    {
        dim3 g(HDIM / 64, T_TOK / 128, 1);
        down_gemm<<<g, 256, DOWN_SMEM, s1>>>(p_ms, shd, out, ISH, HDIM, -1, 3, 0);
    }
    cudaEventRecord(evJ1, s1);

    // s0: routing
    route_kernel<<<T_TOK, 256, 0, s0>>>(x, vm, tgate, igate);
    cudaEventRecord(evRoute, s0);

    // s2: image chain
    cudaStreamWaitEvent(s2, evRoute, 0);
    {
        dim3 g(IIMG / 64, T_TOK / 128, NEXP);
        up_fused<<<g, 256, UP_SMEM, s2>>>(iwg, iwu, p_hi, HDIM, IIMG, 8,
                                          (size_t)T_TOK * IIMG);
    }
    {
        dim3 g(HDIM / 64, T_TOK / 128, NEXP);
        down_gemm<<<g, 256, DOWN_SMEM, s2>>>(p_hi, iwd, p_yt, IIMG, HDIM, 8, 2,
                                             (size_t)T_TOK * IIMG);
    }
    cudaEventRecord(evJ2, s2);

    // s0: text chain
    {
        dim3 g(ITXT / 64, T_TOK / 128, NEXP);
        up_fused<<<g, 256, UP_SMEM, s0>>>(twg, twu, p_ht, HDIM, ITXT, 0,
                                          (size_t)T_TOK * ITXT);
    }
    {
        dim3 g(HDIM / 64, T_TOK / 128, NEXP);
        down_gemm<<<g, 256, DOWN_SMEM, s0>>>(p_ht, twd, p_yt, ITXT, HDIM, 0, 2,
                                             (size_t)T_TOK * ITXT);
    }

    // join + combine
    cudaStreamWaitEvent(s0, evJ1, 0);
    cudaStreamWaitEvent(s0, evJ2, 0);
    {
        int total = T_TOK * HDIM / 4;
        combine_kernel<<<(total + 255) / 256, 256, 0, s0>>>(out);
    }
}

// round 13
// speedup vs baseline: 1.0752x; 1.0007x over previous
#include <cuda_runtime.h>
#include <math.h>

#define T_TOK 2048
#define HDIM  2560
#define NEXP  8
#define ITXT  1536
#define IIMG  512
#define ISH   3072

// ---------------- scratch (static device globals; no allocs allowed) ----------
__device__ int   d_count[16];
__device__ int   d_slot_tok[16][T_TOK];
__device__ float d_slot_wt [16][T_TOK];
__device__ float d_x32 [(size_t)T_TOK * HDIM];            // pre-rounded X (tf32)
__device__ float d_h_text[(size_t)NEXP * T_TOK * ITXT];   // h = swiglu
__device__ float d_h_img [(size_t)NEXP * T_TOK * IIMG];
__device__ float d_mid_sh[(size_t)T_TOK * ISH];
__device__ float d_ytok  [(size_t)T_TOK * 2 * HDIM];

// ---------------- helpers ----------------------------------------------------
__device__ __forceinline__ unsigned ld_tf32(const float* p) {
    unsigned u;
    asm("cvt.rna.tf32.f32 %0, %1;" : "=r"(u) : "f"(*p));
    return u;
}
__device__ __forceinline__ float rnd_tf32(float x) {
    unsigned u;
    asm("cvt.rna.tf32.f32 %0, %1;" : "=r"(u) : "f"(x));
    return __uint_as_float(u);
}

__device__ __forceinline__ void mma_tf32(float c[4], const unsigned a[4],
                                         unsigned b0, unsigned b1) {
    asm volatile(
        "mma.sync.aligned.m16n8k8.row.col.f32.tf32.tf32.f32 "
        "{%0,%1,%2,%3}, {%4,%5,%6,%7}, {%8,%9}, {%0,%1,%2,%3};"
        : "+f"(c[0]), "+f"(c[1]), "+f"(c[2]), "+f"(c[3])
        : "r"(a[0]), "r"(a[1]), "r"(a[2]), "r"(a[3]), "r"(b0), "r"(b1));
}

__device__ __forceinline__ void ldsm_x4(unsigned& r0, unsigned& r1,
                                        unsigned& r2, unsigned& r3,
                                        unsigned addr) {
    asm volatile("ldmatrix.sync.aligned.m8n8.x4.shared.b16 {%0,%1,%2,%3}, [%4];"
                 : "=r"(r0), "=r"(r1), "=r"(r2), "=r"(r3) : "r"(addr));
}

__device__ __forceinline__ void cp16(void* smem, const void* g, int sz) {
    unsigned s = (unsigned)__cvta_generic_to_shared(smem);
    asm volatile("cp.async.cg.shared.global [%0], [%1], 16, %2;"
                 :: "r"(s), "l"(g), "r"(sz));
}
__device__ __forceinline__ void cp_commit() {
    asm volatile("cp.async.commit_group;");
}
template <int N> __device__ __forceinline__ void cp_wait() {
    asm volatile("cp.async.wait_group %0;" :: "n"(N));
}

// ---------------- init / pre-round -------------------------------------------
__global__ void zero_counts_kernel() {
    if (threadIdx.x < 16) d_count[threadIdx.x] = 0;
}

__global__ void preround_x_kernel(const float* __restrict__ x) {
    int i = blockIdx.x * blockDim.x + threadIdx.x;
    const int total = T_TOK * HDIM / 4;
    if (i >= total) return;
    float4 v = reinterpret_cast<const float4*>(x)[i];
    float4 w;
    w.x = rnd_tf32(v.x); w.y = rnd_tf32(v.y);
    w.z = rnd_tf32(v.z); w.w = rnd_tf32(v.w);
    reinterpret_cast<float4*>(d_x32)[i] = w;
}

// ---------------- routing -----------------------------------------------------
// visual_token_mask: bool in reference -> promoted to int32 by the harness.
__global__ void route_kernel(const float* __restrict__ x,
                             const int* __restrict__ vmask,
                             const float* __restrict__ tgate,
                             const float* __restrict__ igate) {
    int t = blockIdx.x;
    int wid = threadIdx.x >> 5, lane = threadIdx.x & 31;
    bool vis = vmask[t] != 0;
    const float* gw = (vis ? igate : tgate) + (size_t)wid * HDIM;
    const float* xr = x + (size_t)t * HDIM;
    float s = 0.f;
    for (int i = lane; i < HDIM; i += 32) s += xr[i] * gw[i];
#pragma unroll
    for (int o = 16; o; o >>= 1) s += __shfl_xor_sync(0xffffffffu, s, o);
    __shared__ float logit[NEXP];
    if (lane == 0) logit[wid] = s;
    __syncthreads();
    if (threadIdx.x == 0) {
        float mx = logit[0];
#pragma unroll
        for (int e = 1; e < NEXP; e++) mx = fmaxf(mx, logit[e]);
        float p[NEXP];
#pragma unroll
        for (int e = 0; e < NEXP; e++) p[e] = expf(logit[e] - mx);
        int i0 = 0;
#pragma unroll
        for (int e = 1; e < NEXP; e++) if (p[e] > p[i0]) i0 = e;
        int i1 = (i0 == 0) ? 1 : 0;
#pragma unroll
        for (int e = 0; e < NEXP; e++)
            if (e != i0 && p[e] > p[i1]) i1 = e;
        float denom = p[i0] + p[i1];
        float w0 = p[i0] / denom;
        float w1 = p[i1] / denom;
        int base = vis ? 8 : 0;
        int g0 = base + i0;
        int g1 = base + i1;
        int pos0 = atomicAdd(&d_count[g0], 1);
        d_slot_tok[g0][pos0] = t * 2 + 0;
        d_slot_wt [g0][pos0] = w0;
        int pos1 = atomicAdd(&d_count[g1], 1);
        d_slot_tok[g1][pos1] = t * 2 + 1;
        d_slot_wt [g1][pos1] = w1;
    }
}

// ---------------- fused up-projection (dual GEMM + SwiGLU) --------------------
// C tile 128x64, BK=32, 2-stage cp.async, 8 warps 4(m) x 2(n), warp 32x32.
// G and U share the A tile and barriers: 128 MMAs per warp-ktile.
// A = d_x32 (pre-rounded). sgbase: -1 -> dense (M=T_TOK); else slot group.
struct UpSmem {
    float As[2][128][36];
    float Bg[2][32][72];
    float Bu[2][32][72];
    int   srcs[128];
};

__global__ __launch_bounds__(256, 2)
void up_fused(const float* __restrict__ Wg_base,
              const float* __restrict__ Wu_base,
              float* __restrict__ H_base,
              int K, int N, int sgbase,
              size_t c_estride) {
    extern __shared__ char smem_raw[];
    UpSmem* sm = reinterpret_cast<UpSmem*>(smem_raw);

    int e = blockIdx.z;
    const int* slot = nullptr;
    int M;
    if (sgbase >= 0) { M = d_count[sgbase + e]; slot = d_slot_tok[sgbase + e]; }
    else             { M = T_TOK; }
    int m0 = blockIdx.y * 128;
    if (m0 >= M) return;
    int n0 = blockIdx.x * 64;

    const float* X  = d_x32;
    const float* Wg = Wg_base + (size_t)e * K * N;
    const float* Wu = Wu_base + (size_t)e * K * N;
    float* H = H_base + (size_t)e * c_estride;

    int tid = threadIdx.x;
    if (tid < 128) {
        int gr = m0 + tid;
        int s = -1;
        if (gr < M) s = slot ? (slot[gr] >> 1) : gr;
        sm->srcs[tid] = s;
    }
    __syncthreads();

    int warp = tid >> 5, lane = tid & 31;
    int wm = warp >> 1, wn = warp & 1;
    int ar = tid >> 3;
    int ac = (tid & 7) * 4;
    int bkr = tid >> 4;
    int bc  = (tid & 15) * 4;

    int asrc[4];
#pragma unroll
    for (int j = 0; j < 4; j++) asrc[j] = sm->srcs[ar + j * 32];

    unsigned As0 = (unsigned)__cvta_generic_to_shared(&sm->As[0][0][0]);
    int arow = wm * 32 + (lane & 7) + ((lane >> 3) & 1) * 8;
    int acol = (lane >> 4) * 4;
    unsigned aaddr0 = As0 + (unsigned)((arow * 36 + acol) * 4);
    unsigned aaddr1 = aaddr0 + 16u * 36u * 4u;
    const unsigned ASTAGE = 128u * 36u * 4u;

    float cg[2][4][4];
    float cu[2][4][4];
#pragma unroll
    for (int a = 0; a < 2; a++)
#pragma unroll
        for (int b = 0; b < 4; b++)
#pragma unroll
            for (int c = 0; c < 4; c++) { cg[a][b][c] = 0.f; cu[a][b][c] = 0.f; }

    auto load_tile = [&](int kk, int st) {
        int k0 = kk * 32;
#pragma unroll
        for (int j = 0; j < 4; j++) {
            int r = ar + j * 32;
            int s = asrc[j];
            cp16(&sm->As[st][r][ac],
                 X + (size_t)(s >= 0 ? s : 0) * K + k0 + ac,
                 s >= 0 ? 16 : 0);
        }
#pragma unroll
        for (int j = 0; j < 2; j++) {
            int kr = bkr + j * 16;
            cp16(&sm->Bg[st][kr][bc], Wg + (size_t)(k0 + kr) * N + n0 + bc, 16);
            cp16(&sm->Bu[st][kr][bc], Wu + (size_t)(k0 + kr) * N + n0 + bc, 16);
        }
        cp_commit();
    };

    int kiters = K >> 5;
    load_tile(0, 0);

    for (int kk = 0; kk < kiters; kk++) {
        int st = kk & 1;
        if (kk + 1 < kiters) {
            load_tile(kk + 1, st ^ 1);
            cp_wait<1>();
        } else {
            cp_wait<0>();
        }
        __syncthreads();

        const float (*Bg2)[72] = sm->Bg[st];
        const float (*Bu2)[72] = sm->Bu[st];
        unsigned stoff = st ? ASTAGE : 0u;

#pragma unroll
        for (int kt = 0; kt < 4; kt++) {
            int kb = kt * 8;
            unsigned a[2][4];
            ldsm_x4(a[0][0], a[0][1], a[0][2], a[0][3], aaddr0 + stoff + kb * 4);
            ldsm_x4(a[1][0], a[1][1], a[1][2], a[1][3], aaddr1 + stoff + kb * 4);
#pragma unroll
            for (int fn = 0; fn < 4; fn++) {
                int bcc = wn * 32 + fn * 8 + (lane >> 2);
                int brr = kb + (lane & 3);
                unsigned bg0 = ld_tf32(&Bg2[brr][bcc]);
                unsigned bg1 = ld_tf32(&Bg2[brr + 4][bcc]);
                unsigned bu0 = ld_tf32(&Bu2[brr][bcc]);
                unsigned bu1 = ld_tf32(&Bu2[brr + 4][bcc]);
                mma_tf32(cg[0][fn], a[0], bg0, bg1);
                mma_tf32(cg[1][fn], a[1], bg0, bg1);
                mma_tf32(cu[0][fn], a[0], bu0, bu1);
                mma_tf32(cu[1][fn], a[1], bu0, bu1);
            }
        }
        __syncthreads();
    }

    // epilogue: h = rnd_tf32(silu(g) * u)
#pragma unroll
    for (int fm = 0; fm < 2; fm++) {
        int rbase = m0 + wm * 32 + fm * 16 + (lane >> 2);
#pragma unroll
        for (int fn = 0; fn < 4; fn++) {
            int col = n0 + wn * 32 + fn * 8 + (lane & 3) * 2;
#pragma unroll
            for (int half = 0; half < 2; half++) {
                int r = rbase + half * 8;
                if (r >= M) continue;
                float g0 = cg[fm][fn][half * 2 + 0];
                float g1 = cg[fm][fn][half * 2 + 1];
                float u0 = cu[fm][fn][half * 2 + 0];
                float u1 = cu[fm][fn][half * 2 + 1];
                float h0 = rnd_tf32(g0 / (1.f + expf(-g0)) * u0);
                float h1 = rnd_tf32(g1 / (1.f + expf(-g1)) * u1);
                *reinterpret_cast<float2*>(H + (size_t)r * N + col) =
                    make_float2(h0, h1);
            }
        }
    }
}

// ---------------- down-projection (R9 geometry, best known) -------------------
// epi: 2 = scatter+scale into y_tok, 3 = direct store.
struct GSmem {
    float As[2][128][36];
    float Bs[2][32][72];
};

__global__ __launch_bounds__(256, 3)
void down_gemm(const float* __restrict__ A_base,
               const float* __restrict__ B_base,
               float* __restrict__ C_base,
               int K, int N, int sgbase, int epi,
               size_t a_estride) {
    extern __shared__ char smem_raw[];
    GSmem* sm = reinterpret_cast<GSmem*>(smem_raw);

    int e = blockIdx.z;
    const int* slot = nullptr;
    const float* wts = nullptr;
    int M;
    if (sgbase >= 0) {
        M = d_count[sgbase + e];
        slot = d_slot_tok[sgbase + e];
        wts  = d_slot_wt [sgbase + e];
    } else {
        M = T_TOK;
    }
    int m0 = blockIdx.y * 128;
    if (m0 >= M) return;
    int n0 = blockIdx.x * 64;

    const float* A = A_base + (size_t)e * a_estride;
    const float* B = B_base + (size_t)e * K * N;
    float* C = C_base;

    int tid = threadIdx.x;
    int warp = tid >> 5, lane = tid & 31;
    int wm = warp >> 1, wn = warp & 1;
    int ar = tid >> 3;
    int ac = (tid & 7) * 4;
    int bkr = tid >> 4;
    int bc  = (tid & 15) * 4;

    unsigned As0 = (unsigned)__cvta_generic_to_shared(&sm->As[0][0][0]);
    int arow = wm * 32 + (lane & 7) + ((lane >> 3) & 1) * 8;
    int acol = (lane >> 4) * 4;
    unsigned aaddr0 = As0 + (unsigned)((arow * 36 + acol) * 4);
    unsigned aaddr1 = aaddr0 + 16u * 36u * 4u;
    const unsigned ASTAGE = 128u * 36u * 4u;

    float cc[2][4][4];
#pragma unroll
    for (int a = 0; a < 2; a++)
#pragma unroll
        for (int b = 0; b < 4; b++)
#pragma unroll
            for (int c = 0; c < 4; c++) cc[a][b][c] = 0.f;

    auto load_tile = [&](int kk, int st) {
        int k0 = kk * 32;
#pragma unroll
        for (int j = 0; j < 4; j++) {
            int r = ar + j * 32;
            int gr = m0 + r;
            cp16(&sm->As[st][r][ac],
                 A + (size_t)(gr < M ? gr : 0) * K + k0 + ac,
                 gr < M ? 16 : 0);
        }
#pragma unroll
        for (int j = 0; j < 2; j++) {
            int kr = bkr + j * 16;
            cp16(&sm->Bs[st][kr][bc], B + (size_t)(k0 + kr) * N + n0 + bc, 16);
        }
        cp_commit();
    };

    int kiters = K >> 5;
    load_tile(0, 0);

    for (int kk = 0; kk < kiters; kk++) {
        int st = kk & 1;
        if (kk + 1 < kiters) {
            load_tile(kk + 1, st ^ 1);
            cp_wait<1>();
        } else {
            cp_wait<0>();
        }
        __syncthreads();

        const float (*Bs2)[72] = sm->Bs[st];
        unsigned stoff = st ? ASTAGE : 0u;

#pragma unroll
        for (int kt = 0; kt < 4; kt++) {
            int kb = kt * 8;
            unsigned a[2][4];
            ldsm_x4(a[0][0], a[0][1], a[0][2], a[0][3], aaddr0 + stoff + kb * 4);
            ldsm_x4(a[1][0], a[1][1], a[1][2], a[1][3], aaddr1 + stoff + kb * 4);
#pragma unroll
            for (int fn = 0; fn < 4; fn++) {
                int bcc = wn * 32 + fn * 8 + (lane >> 2);
                int brr = kb + (lane & 3);
                unsigned b0 = ld_tf32(&Bs2[brr][bcc]);
                unsigned b1 = ld_tf32(&Bs2[brr + 4][bcc]);
                mma_tf32(cc[0][fn], a[0], b0, b1);
                mma_tf32(cc[1][fn], a[1], b0, b1);
            }
        }
        __syncthreads();
    }

#pragma unroll
    for (int fm = 0; fm < 2; fm++) {
        int rbase = m0 + wm * 32 + fm * 16 + (lane >> 2);
#pragma unroll
        for (int fn = 0; fn < 4; fn++) {
            int col = n0 + wn * 32 + fn * 8 + (lane & 3) * 2;
#pragma unroll
            for (int half = 0; half < 2; half++) {
                int r = rbase + half * 8;
                if (r >= M) continue;
                float v0 = cc[fm][fn][half * 2 + 0];
                float v1 = cc[fm][fn][half * 2 + 1];
                if (epi == 2) {
                    int dst = slot[r];
                    float s = wts[r];
                    *reinterpret_cast<float2*>(C + (size_t)dst * N + col) =
                        make_float2(s * v0, s * v1);
                } else {
                    *reinterpret_cast<float2*>(C + (size_t)r * N + col) =
                        make_float2(v0, v1);
                }
            }
        }
    }
}

// ---------------- final combine: out += y_tok[2t] + y_tok[2t+1] --------------
__global__ void combine_kernel(float* __restrict__ out) {
    int i = blockIdx.x * blockDim.x + threadIdx.x;
    const int total = T_TOK * HDIM / 4;
    if (i >= total) return;
    int row = i / (HDIM / 4);
    int c4 = i % (HDIM / 4);
    const float4* y0 = reinterpret_cast<const float4*>(d_ytok + (size_t)(2 * row) * HDIM) + c4;
    const float4* y1 = reinterpret_cast<const float4*>(d_ytok + (size_t)(2 * row + 1) * HDIM) + c4;
    float4 o = reinterpret_cast<float4*>(out)[i];
    float4 a = *y0, b = *y1;
    o.x += a.x + b.x; o.y += a.y + b.y;
    o.z += a.z + b.z; o.w += a.w + b.w;
    reinterpret_cast<float4*>(out)[i] = o;
}

// ---------------- launch ------------------------------------------------------
extern "C" void kernel_launch(void* const* d_in, const int* in_sizes, int n_in,
                              void* d_out, int out_size) {
    const float* x     = (const float*)d_in[0];
    const int*   vm    = (const int*)d_in[1];      // bool promoted to int32
    const float* tgate = (const float*)d_in[2];
    const float* twg   = (const float*)d_in[3];
    const float* twu   = (const float*)d_in[4];
    const float* twd   = (const float*)d_in[5];
    const float* igate = (const float*)d_in[6];
    const float* iwg   = (const float*)d_in[7];
    const float* iwu   = (const float*)d_in[8];
    const float* iwd   = (const float*)d_in[9];
    const float* shg   = (const float*)d_in[10];
    const float* shu   = (const float*)d_in[11];
    const float* shd   = (const float*)d_in[12];
    float* out = (float*)d_out;

    const int UP_SMEM   = (int)sizeof(UpSmem);
    const int DOWN_SMEM = (int)sizeof(GSmem);

    static bool init = false;
    static cudaStream_t s1, s2;
    static cudaEvent_t evRoot, evRoute, evJ1, evJ2;
    if (!init) {
        cudaStreamCreateWithFlags(&s1, cudaStreamNonBlocking);
        cudaStreamCreateWithFlags(&s2, cudaStreamNonBlocking);
        cudaEventCreateWithFlags(&evRoot,  cudaEventDisableTiming);
        cudaEventCreateWithFlags(&evRoute, cudaEventDisableTiming);
        cudaEventCreateWithFlags(&evJ1,    cudaEventDisableTiming);
        cudaEventCreateWithFlags(&evJ2,    cudaEventDisableTiming);
        cudaFuncSetAttribute(up_fused,
            cudaFuncAttributeMaxDynamicSharedMemorySize, UP_SMEM);
        cudaFuncSetAttribute(down_gemm,
            cudaFuncAttributeMaxDynamicSharedMemorySize, DOWN_SMEM);
        init = true;
    }

    cudaStream_t s0 = 0;   // captured legacy stream

    static float *p_x32 = nullptr, *p_ht, *p_hi, *p_ms, *p_yt;
    if (!p_x32) {
        cudaGetSymbolAddress((void**)&p_x32, d_x32);
        cudaGetSymbolAddress((void**)&p_ht,  d_h_text);
        cudaGetSymbolAddress((void**)&p_hi,  d_h_img);
        cudaGetSymbolAddress((void**)&p_ms,  d_mid_sh);
        cudaGetSymbolAddress((void**)&p_yt,  d_ytok);
    }

    // prologue on s0
    zero_counts_kernel<<<1, 32, 0, s0>>>();
    {
        int total = T_TOK * HDIM / 4;
        preround_x_kernel<<<(total + 255) / 256, 256, 0, s0>>>(x);
    }
    cudaEventRecord(evRoot, s0);

    // s1: shared chain (independent of routing)
    cudaStreamWaitEvent(s1, evRoot, 0);
    {
        dim3 g(ISH / 64, T_TOK / 128, 1);
        up_fused<<<g, 256, UP_SMEM, s1>>>(shg, shu, p_ms, HDIM, ISH, -1, 0);
    }
    {
        dim3 g(HDIM / 64, T_TOK / 128, 1);
        down_gemm<<<g, 256, DOWN_SMEM, s1>>>(p_ms, shd, out, ISH, HDIM, -1, 3, 0);
    }
    cudaEventRecord(evJ1, s1);

    // s0: routing
    route_kernel<<<T_TOK, 256, 0, s0>>>(x, vm, tgate, igate);
    cudaEventRecord(evRoute, s0);

    // s2: image chain
    cudaStreamWaitEvent(s2, evRoute, 0);
    {
        dim3 g(IIMG / 64, T_TOK / 128, NEXP);
        up_fused<<<g, 256, UP_SMEM, s2>>>(iwg, iwu, p_hi, HDIM, IIMG, 8,
                                          (size_t)T_TOK * IIMG);
    }
    {
        dim3 g(HDIM / 64, T_TOK / 128, NEXP);
        down_gemm<<<g, 256, DOWN_SMEM, s2>>>(p_hi, iwd, p_yt, IIMG, HDIM, 8, 2,
                                             (size_t)T_TOK * IIMG);
    }
    cudaEventRecord(evJ2, s2);

    // s0: text chain
    {
        dim3 g(ITXT / 64, T_TOK / 128, NEXP);
        up_fused<<<g, 256, UP_SMEM, s0>>>(twg, twu, p_ht, HDIM, ITXT, 0,
                                          (size_t)T_TOK * ITXT);
    }
    {
        dim3 g(HDIM / 64, T_TOK / 128, NEXP);
        down_gemm<<<g, 256, DOWN_SMEM, s0>>>(p_ht, twd, p_yt, ITXT, HDIM, 0, 2,
                                             (size_t)T_TOK * ITXT);
    }

    // join + combine
    cudaStreamWaitEvent(s0, evJ1, 0);
    cudaStreamWaitEvent(s0, evJ2, 0);
    {
        int total = T_TOK * HDIM / 4;
        combine_kernel<<<(total + 255) / 256, 256, 0, s0>>>(out);
    }
}

// round 15
// speedup vs baseline: 1.0927x; 1.0163x over previous
#include <cuda_runtime.h>
#include <math.h>

#define T_TOK 2048
#define HDIM  2560
#define NEXP  8
#define ITXT  1536
#define IIMG  512
#define ISH   3072

// ---------------- scratch (static device globals; no allocs allowed) ----------
__device__ int   d_count[16];
__device__ int   d_slot_tok[16][T_TOK];
__device__ float d_slot_wt [16][T_TOK];
__device__ float d_x32 [(size_t)T_TOK * HDIM];            // pre-rounded X (tf32)
__device__ float d_h_text[(size_t)NEXP * T_TOK * ITXT];   // h = swiglu
__device__ float d_h_img [(size_t)NEXP * T_TOK * IIMG];
__device__ float d_mid_sh[(size_t)T_TOK * ISH];
__device__ float d_ytok  [(size_t)T_TOK * 2 * HDIM];

// ---------------- helpers ----------------------------------------------------
__device__ __forceinline__ unsigned ld_tf32(const float* p) {
    unsigned u;
    asm("cvt.rna.tf32.f32 %0, %1;" : "=r"(u) : "f"(*p));
    return u;
}
__device__ __forceinline__ float rnd_tf32(float x) {
    unsigned u;
    asm("cvt.rna.tf32.f32 %0, %1;" : "=r"(u) : "f"(x));
    return __uint_as_float(u);
}

__device__ __forceinline__ void mma_tf32(float c[4], const unsigned a[4],
                                         unsigned b0, unsigned b1) {
    asm volatile(
        "mma.sync.aligned.m16n8k8.row.col.f32.tf32.tf32.f32 "
        "{%0,%1,%2,%3}, {%4,%5,%6,%7}, {%8,%9}, {%0,%1,%2,%3};"
        : "+f"(c[0]), "+f"(c[1]), "+f"(c[2]), "+f"(c[3])
        : "r"(a[0]), "r"(a[1]), "r"(a[2]), "r"(a[3]), "r"(b0), "r"(b1));
}

__device__ __forceinline__ void ldsm_x4(unsigned& r0, unsigned& r1,
                                        unsigned& r2, unsigned& r3,
                                        unsigned addr) {
    asm volatile("ldmatrix.sync.aligned.m8n8.x4.shared.b16 {%0,%1,%2,%3}, [%4];"
                 : "=r"(r0), "=r"(r1), "=r"(r2), "=r"(r3) : "r"(addr));
}

__device__ __forceinline__ void cp16(void* smem, const void* g, int sz) {
    unsigned s = (unsigned)__cvta_generic_to_shared(smem);
    asm volatile("cp.async.cg.shared.global [%0], [%1], 16, %2;"
                 :: "r"(s), "l"(g), "r"(sz));
}
__device__ __forceinline__ void cp_commit() {
    asm volatile("cp.async.commit_group;");
}
template <int N> __device__ __forceinline__ void cp_wait() {
    asm volatile("cp.async.wait_group %0;" :: "n"(N));
}

// ---------------- init / pre-round -------------------------------------------
__global__ void zero_counts_kernel() {
    if (threadIdx.x < 16) d_count[threadIdx.x] = 0;
}

__global__ void preround_x_kernel(const float* __restrict__ x) {
    int i = blockIdx.x * blockDim.x + threadIdx.x;
    const int total = T_TOK * HDIM / 4;
    if (i >= total) return;
    float4 v = reinterpret_cast<const float4*>(x)[i];
    float4 w;
    w.x = rnd_tf32(v.x); w.y = rnd_tf32(v.y);
    w.z = rnd_tf32(v.z); w.w = rnd_tf32(v.w);
    reinterpret_cast<float4*>(d_x32)[i] = w;
}

// ---------------- routing -----------------------------------------------------
// visual_token_mask: bool in reference -> promoted to int32 by the harness.
__global__ void route_kernel(const float* __restrict__ x,
                             const int* __restrict__ vmask,
                             const float* __restrict__ tgate,
                             const float* __restrict__ igate) {
    int t = blockIdx.x;
    int wid = threadIdx.x >> 5, lane = threadIdx.x & 31;
    bool vis = vmask[t] != 0;
    const float* gw = (vis ? igate : tgate) + (size_t)wid * HDIM;
    const float* xr = x + (size_t)t * HDIM;
    float s = 0.f;
    for (int i = lane; i < HDIM; i += 32) s += xr[i] * gw[i];
#pragma unroll
    for (int o = 16; o; o >>= 1) s += __shfl_xor_sync(0xffffffffu, s, o);
    __shared__ float logit[NEXP];
    if (lane == 0) logit[wid] = s;
    __syncthreads();
    if (threadIdx.x == 0) {
        float mx = logit[0];
#pragma unroll
        for (int e = 1; e < NEXP; e++) mx = fmaxf(mx, logit[e]);
        float p[NEXP];
#pragma unroll
        for (int e = 0; e < NEXP; e++) p[e] = expf(logit[e] - mx);
        int i0 = 0;
#pragma unroll
        for (int e = 1; e < NEXP; e++) if (p[e] > p[i0]) i0 = e;
        int i1 = (i0 == 0) ? 1 : 0;
#pragma unroll
        for (int e = 0; e < NEXP; e++)
            if (e != i0 && p[e] > p[i1]) i1 = e;
        float denom = p[i0] + p[i1];
        float w0 = p[i0] / denom;
        float w1 = p[i1] / denom;
        int base = vis ? 8 : 0;
        int g0 = base + i0;
        int g1 = base + i1;
        int pos0 = atomicAdd(&d_count[g0], 1);
        d_slot_tok[g0][pos0] = t * 2 + 0;
        d_slot_wt [g0][pos0] = w0;
        int pos1 = atomicAdd(&d_count[g1], 1);
        d_slot_tok[g1][pos1] = t * 2 + 1;
        d_slot_wt [g1][pos1] = w1;
    }
}

// ---------------- fused up-projection (dual GEMM + SwiGLU) --------------------
// C tile 128x64(G)+128x64(U), BK=32, 2-stage cp.async, 8 warps 4(m) x 2(n).
// G and U share the A tile and barriers: 128 MMAs per warp-ktile.
struct UpSmem {
    float As[2][128][36];
    float Bg[2][32][72];
    float Bu[2][32][72];
    int   srcs[128];
};

__global__ __launch_bounds__(256, 2)
void up_fused(const float* __restrict__ Wg_base,
              const float* __restrict__ Wu_base,
              float* __restrict__ H_base,
              int K, int N, int sgbase,
              size_t c_estride) {
    extern __shared__ char smem_raw[];
    UpSmem* sm = reinterpret_cast<UpSmem*>(smem_raw);

    int e = blockIdx.z;
    const int* slot = nullptr;
    int M;
    if (sgbase >= 0) { M = d_count[sgbase + e]; slot = d_slot_tok[sgbase + e]; }
    else             { M = T_TOK; }
    int m0 = blockIdx.y * 128;
    if (m0 >= M) return;
    int n0 = blockIdx.x * 64;

    const float* X  = d_x32;
    const float* Wg = Wg_base + (size_t)e * K * N;
    const float* Wu = Wu_base + (size_t)e * K * N;
    float* H = H_base + (size_t)e * c_estride;

    int tid = threadIdx.x;
    if (tid < 128) {
        int gr = m0 + tid;
        int s = -1;
        if (gr < M) s = slot ? (slot[gr] >> 1) : gr;
        sm->srcs[tid] = s;
    }
    __syncthreads();

    int warp = tid >> 5, lane = tid & 31;
    int wm = warp >> 1, wn = warp & 1;
    int ar = tid >> 3;
    int ac = (tid & 7) * 4;
    int bkr = tid >> 4;
    int bc  = (tid & 15) * 4;

    int asrc[4];
#pragma unroll
    for (int j = 0; j < 4; j++) asrc[j] = sm->srcs[ar + j * 32];

    unsigned As0 = (unsigned)__cvta_generic_to_shared(&sm->As[0][0][0]);
    int arow = wm * 32 + (lane & 7) + ((lane >> 3) & 1) * 8;
    int acol = (lane >> 4) * 4;
    unsigned aaddr0 = As0 + (unsigned)((arow * 36 + acol) * 4);
    unsigned aaddr1 = aaddr0 + 16u * 36u * 4u;
    const unsigned ASTAGE = 128u * 36u * 4u;

    float cg[2][4][4];
    float cu[2][4][4];
#pragma unroll
    for (int a = 0; a < 2; a++)
#pragma unroll
        for (int b = 0; b < 4; b++)
#pragma unroll
            for (int c = 0; c < 4; c++) { cg[a][b][c] = 0.f; cu[a][b][c] = 0.f; }

    auto load_tile = [&](int kk, int st) {
        int k0 = kk * 32;
#pragma unroll
        for (int j = 0; j < 4; j++) {
            int r = ar + j * 32;
            int s = asrc[j];
            cp16(&sm->As[st][r][ac],
                 X + (size_t)(s >= 0 ? s : 0) * K + k0 + ac,
                 s >= 0 ? 16 : 0);
        }
#pragma unroll
        for (int j = 0; j < 2; j++) {
            int kr = bkr + j * 16;
            cp16(&sm->Bg[st][kr][bc], Wg + (size_t)(k0 + kr) * N + n0 + bc, 16);
            cp16(&sm->Bu[st][kr][bc], Wu + (size_t)(k0 + kr) * N + n0 + bc, 16);
        }
        cp_commit();
    };

    int kiters = K >> 5;
    load_tile(0, 0);

    for (int kk = 0; kk < kiters; kk++) {
        int st = kk & 1;
        if (kk + 1 < kiters) {
            load_tile(kk + 1, st ^ 1);
            cp_wait<1>();
        } else {
            cp_wait<0>();
        }
        __syncthreads();

        const float (*Bg2)[72] = sm->Bg[st];
        const float (*Bu2)[72] = sm->Bu[st];
        unsigned stoff = st ? ASTAGE : 0u;

#pragma unroll
        for (int kt = 0; kt < 4; kt++) {
            int kb = kt * 8;
            unsigned a[2][4];
            ldsm_x4(a[0][0], a[0][1], a[0][2], a[0][3], aaddr0 + stoff + kb * 4);
            ldsm_x4(a[1][0], a[1][1], a[1][2], a[1][3], aaddr1 + stoff + kb * 4);
#pragma unroll
            for (int fn = 0; fn < 4; fn++) {
                int bcc = wn * 32 + fn * 8 + (lane >> 2);
                int brr = kb + (lane & 3);
                unsigned bg0 = ld_tf32(&Bg2[brr][bcc]);
                unsigned bg1 = ld_tf32(&Bg2[brr + 4][bcc]);
                unsigned bu0 = ld_tf32(&Bu2[brr][bcc]);
                unsigned bu1 = ld_tf32(&Bu2[brr + 4][bcc]);
                mma_tf32(cg[0][fn], a[0], bg0, bg1);
                mma_tf32(cg[1][fn], a[1], bg0, bg1);
                mma_tf32(cu[0][fn], a[0], bu0, bu1);
                mma_tf32(cu[1][fn], a[1], bu0, bu1);
            }
        }
        __syncthreads();
    }

    // epilogue: h = rnd_tf32(silu(g) * u)
#pragma unroll
    for (int fm = 0; fm < 2; fm++) {
        int rbase = m0 + wm * 32 + fm * 16 + (lane >> 2);
#pragma unroll
        for (int fn = 0; fn < 4; fn++) {
            int col = n0 + wn * 32 + fn * 8 + (lane & 3) * 2;
#pragma unroll
            for (int half = 0; half < 2; half++) {
                int r = rbase + half * 8;
                if (r >= M) continue;
                float g0 = cg[fm][fn][half * 2 + 0];
                float g1 = cg[fm][fn][half * 2 + 1];
                float u0 = cu[fm][fn][half * 2 + 0];
                float u1 = cu[fm][fn][half * 2 + 1];
                float h0 = rnd_tf32(g0 / (1.f + expf(-g0)) * u0);
                float h1 = rnd_tf32(g1 / (1.f + expf(-g1)) * u1);
                *reinterpret_cast<float2*>(H + (size_t)r * N + col) =
                    make_float2(h0, h1);
            }
        }
    }
}

// ---------------- down-projection: BN=128 wide tile ---------------------------
// C tile 128x128, BK=32, 8 warps 4(m) x 2(n), warp tile 32x64 (fm=2, fn=8).
// epi: 2 = scatter+scale into y_tok, 3 = direct store. N must be = HDIM here.
struct DnSmem {
    float As[2][128][36];
    float Bs[2][32][136];
};

__global__ __launch_bounds__(256, 2)
void down_gemm(const float* __restrict__ A_base,
               const float* __restrict__ B_base,
               float* __restrict__ C_base,
               int K, int N, int sgbase, int epi,
               size_t a_estride) {
    extern __shared__ char smem_raw[];
    DnSmem* sm = reinterpret_cast<DnSmem*>(smem_raw);

    int e = blockIdx.z;
    const int* slot = nullptr;
    const float* wts = nullptr;
    int M;
    if (sgbase >= 0) {
        M = d_count[sgbase + e];
        slot = d_slot_tok[sgbase + e];
        wts  = d_slot_wt [sgbase + e];
    } else {
        M = T_TOK;
    }
    int m0 = blockIdx.y * 128;
    if (m0 >= M) return;
    int n0 = blockIdx.x * 128;

    const float* A = A_base + (size_t)e * a_estride;
    const float* B = B_base + (size_t)e * K * N;
    float* C = C_base;

    int tid = threadIdx.x;
    int warp = tid >> 5, lane = tid & 31;
    int wm = warp >> 1, wn = warp & 1;
    int ar = tid >> 3;            // A loader rows 0..31 (stride 32)
    int ac = (tid & 7) * 4;
    int bkr = tid >> 3;           // B loader k-row 0..31
    int bcc8 = tid & 7;           // B chunk base (of 32 16B-chunks/row)

    unsigned As0 = (unsigned)__cvta_generic_to_shared(&sm->As[0][0][0]);
    int arow = wm * 32 + (lane & 7) + ((lane >> 3) & 1) * 8;
    int acol = (lane >> 4) * 4;
    unsigned aaddr0 = As0 + (unsigned)((arow * 36 + acol) * 4);
    unsigned aaddr1 = aaddr0 + 16u * 36u * 4u;
    const unsigned ASTAGE = 128u * 36u * 4u;

    float cc[2][8][4];
#pragma unroll
    for (int a = 0; a < 2; a++)
#pragma unroll
        for (int b = 0; b < 8; b++)
#pragma unroll
            for (int c = 0; c < 4; c++) cc[a][b][c] = 0.f;

    auto load_tile = [&](int kk, int st) {
        int k0 = kk * 32;
#pragma unroll
        for (int j = 0; j < 4; j++) {
            int r = ar + j * 32;
            int gr = m0 + r;
            cp16(&sm->As[st][r][ac],
                 A + (size_t)(gr < M ? gr : 0) * K + k0 + ac,
                 gr < M ? 16 : 0);
        }
        const float* brow = B + (size_t)(k0 + bkr) * N + n0;
#pragma unroll
        for (int j = 0; j < 4; j++) {
            int c = (bcc8 + j * 8) * 4;
            cp16(&sm->Bs[st][bkr][c], brow + c, 16);
        }
        cp_commit();
    };

    int kiters = K >> 5;
    load_tile(0, 0);

    for (int kk = 0; kk < kiters; kk++) {
        int st = kk & 1;
        if (kk + 1 < kiters) {
            load_tile(kk + 1, st ^ 1);
            cp_wait<1>();
        } else {
            cp_wait<0>();
        }
        __syncthreads();

        const float (*Bs2)[136] = sm->Bs[st];
        unsigned stoff = st ? ASTAGE : 0u;

#pragma unroll
        for (int kt = 0; kt < 4; kt++) {
            int kb = kt * 8;
            unsigned a[2][4];
            ldsm_x4(a[0][0], a[0][1], a[0][2], a[0][3], aaddr0 + stoff + kb * 4);
            ldsm_x4(a[1][0], a[1][1], a[1][2], a[1][3], aaddr1 + stoff + kb * 4);
#pragma unroll
            for (int fn = 0; fn < 8; fn++) {
                int bcc = wn * 64 + fn * 8 + (lane >> 2);
                int brr = kb + (lane & 3);
                unsigned b0 = ld_tf32(&Bs2[brr][bcc]);
                unsigned b1 = ld_tf32(&Bs2[brr + 4][bcc]);
                mma_tf32(cc[0][fn], a[0], b0, b1);
                mma_tf32(cc[1][fn], a[1], b0, b1);
            }
        }
        __syncthreads();
    }

#pragma unroll
    for (int fm = 0; fm < 2; fm++) {
        int rbase = m0 + wm * 32 + fm * 16 + (lane >> 2);
#pragma unroll
        for (int fn = 0; fn < 8; fn++) {
            int col = n0 + wn * 64 + fn * 8 + (lane & 3) * 2;
#pragma unroll
            for (int half = 0; half < 2; half++) {
                int r = rbase + half * 8;
                if (r >= M) continue;
                float v0 = cc[fm][fn][half * 2 + 0];
                float v1 = cc[fm][fn][half * 2 + 1];
                if (epi == 2) {
                    int dst = slot[r];
                    float s = wts[r];
                    *reinterpret_cast<float2*>(C + (size_t)dst * N + col) =
                        make_float2(s * v0, s * v1);
                } else {
                    *reinterpret_cast<float2*>(C + (size_t)r * N + col) =
                        make_float2(v0, v1);
                }
            }
        }
    }
}

// ---------------- final combine: out += y_tok[2t] + y_tok[2t+1] --------------
__global__ void combine_kernel(float* __restrict__ out) {
    int i = blockIdx.x * blockDim.x + threadIdx.x;
    const int total = T_TOK * HDIM / 4;
    if (i >= total) return;
    int row = i / (HDIM / 4);
    int c4 = i % (HDIM / 4);
    const float4* y0 = reinterpret_cast<const float4*>(d_ytok + (size_t)(2 * row) * HDIM) + c4;
    const float4* y1 = reinterpret_cast<const float4*>(d_ytok + (size_t)(2 * row + 1) * HDIM) + c4;
    float4 o = reinterpret_cast<float4*>(out)[i];
    float4 a = *y0, b = *y1;
    o.x += a.x + b.x; o.y += a.y + b.y;
    o.z += a.z + b.z; o.w += a.w + b.w;
    reinterpret_cast<float4*>(out)[i] = o;
}

// ---------------- launch ------------------------------------------------------
extern "C" void kernel_launch(void* const* d_in, const int* in_sizes, int n_in,
                              void* d_out, int out_size) {
    const float* x     = (const float*)d_in[0];
    const int*   vm    = (const int*)d_in[1];      // bool promoted to int32
    const float* tgate = (const float*)d_in[2];
    const float* twg   = (const float*)d_in[3];
    const float* twu   = (const float*)d_in[4];
    const float* twd   = (const float*)d_in[5];
    const float* igate = (const float*)d_in[6];
    const float* iwg   = (const float*)d_in[7];
    const float* iwu   = (const float*)d_in[8];
    const float* iwd   = (const float*)d_in[9];
    const float* shg   = (const float*)d_in[10];
    const float* shu   = (const float*)d_in[11];
    const float* shd   = (const float*)d_in[12];
    float* out = (float*)d_out;

    const int UP_SMEM   = (int)sizeof(UpSmem);
    const int DOWN_SMEM = (int)sizeof(DnSmem);

    static bool init = false;
    static cudaStream_t s1, s2;
    static cudaEvent_t evRoot, evRoute, evJ1, evJ2;
    if (!init) {
        cudaStreamCreateWithFlags(&s1, cudaStreamNonBlocking);
        cudaStreamCreateWithFlags(&s2, cudaStreamNonBlocking);
        cudaEventCreateWithFlags(&evRoot,  cudaEventDisableTiming);
        cudaEventCreateWithFlags(&evRoute, cudaEventDisableTiming);
        cudaEventCreateWithFlags(&evJ1,    cudaEventDisableTiming);
        cudaEventCreateWithFlags(&evJ2,    cudaEventDisableTiming);
        cudaFuncSetAttribute(up_fused,
            cudaFuncAttributeMaxDynamicSharedMemorySize, UP_SMEM);
        cudaFuncSetAttribute(down_gemm,
            cudaFuncAttributeMaxDynamicSharedMemorySize, DOWN_SMEM);
        init = true;
    }

    cudaStream_t s0 = 0;   // captured legacy stream

    static float *p_x32 = nullptr, *p_ht, *p_hi, *p_ms, *p_yt;
    if (!p_x32) {
        cudaGetSymbolAddress((void**)&p_x32, d_x32);
        cudaGetSymbolAddress((void**)&p_ht,  d_h_text);
        cudaGetSymbolAddress((void**)&p_hi,  d_h_img);
        cudaGetSymbolAddress((void**)&p_ms,  d_mid_sh);
        cudaGetSymbolAddress((void**)&p_yt,  d_ytok);
    }

    // prologue on s0
    zero_counts_kernel<<<1, 32, 0, s0>>>();
    {
        int total = T_TOK * HDIM / 4;
        preround_x_kernel<<<(total + 255) / 256, 256, 0, s0>>>(x);
    }
    cudaEventRecord(evRoot, s0);

    // s1: shared chain (independent of routing)
    cudaStreamWaitEvent(s1, evRoot, 0);
    {
        dim3 g(ISH / 64, T_TOK / 128, 1);
        up_fused<<<g, 256, UP_SMEM, s1>>>(shg, shu, p_ms, HDIM, ISH, -1, 0);
    }
    {
        dim3 g(HDIM / 128, T_TOK / 128, 1);
        down_gemm<<<g, 256, DOWN_SMEM, s1>>>(p_ms, shd, out, ISH, HDIM, -1, 3, 0);
    }
    cudaEventRecord(evJ1, s1);

    // s0: routing
    route_kernel<<<T_TOK, 256, 0, s0>>>(x, vm, tgate, igate);
    cudaEventRecord(evRoute, s0);

    // s2: image chain
    cudaStreamWaitEvent(s2, evRoute, 0);
    {
        dim3 g(IIMG / 64, T_TOK / 128, NEXP);
        up_fused<<<g, 256, UP_SMEM, s2>>>(iwg, iwu, p_hi, HDIM, IIMG, 8,
                                          (size_t)T_TOK * IIMG);
    }
    {
        dim3 g(HDIM / 128, T_TOK / 128, NEXP);
        down_gemm<<<g, 256, DOWN_SMEM, s2>>>(p_hi, iwd, p_yt, IIMG, HDIM, 8, 2,
                                             (size_t)T_TOK * IIMG);
    }
    cudaEventRecord(evJ2, s2);

    // s0: text chain
    {
        dim3 g(ITXT / 64, T_TOK / 128, NEXP);
        up_fused<<<g, 256, UP_SMEM, s0>>>(twg, twu, p_ht, HDIM, ITXT, 0,
                                          (size_t)T_TOK * ITXT);
    }
    {
        dim3 g(HDIM / 128, T_TOK / 128, NEXP);
        down_gemm<<<g, 256, DOWN_SMEM, s0>>>(p_ht, twd, p_yt, ITXT, HDIM, 0, 2,
                                             (size_t)T_TOK * ITXT);
    }

    // join + combine
    cudaStreamWaitEvent(s0, evJ1, 0);
    cudaStreamWaitEvent(s0, evJ2, 0);
    {
        int total = T_TOK * HDIM / 4;
        combine_kernel<<<(total + 255) / 256, 256, 0, s0>>>(out);
    }
}